// round 2
// baseline (speedup 1.0000x reference)
#include <cuda_runtime.h>
#include <math.h>

#define N_NODES 100000
#define N_EDGES 1600000
#define F       128
#define OUTC    64

// ---------------- scratch (static device globals; no allocation) ----------------
__device__ float g_U[(size_t)N_NODES * F];     // u = inv_sqrt * (h @ W)
__device__ float g_H[(size_t)N_NODES * F];     // layer activations
__device__ int   g_srcSorted[N_EDGES];         // CSR: src indices grouped by dst
__device__ int   g_cnt[N_NODES];               // in-degree (edges only)
__device__ int   g_rowstart[N_NODES + 1];      // CSR row offsets
__device__ int   g_cursor[N_NODES];            // scatter cursors
__device__ float g_invs[N_NODES];              // deg^{-1/2}, deg = cnt+1 (self loop)
__device__ int   g_is64;                       // edge_index dtype flag

// ---------------- dtype probe ----------------
// If edge_index is int64 with values in [0, N_NODES), every odd 32-bit word of
// the first pairs is zero. If it's int32, odd words are uniform node indices.
__global__ void detect_kernel(const int* __restrict__ ei_raw) {
    if (blockIdx.x == 0 && threadIdx.x == 0) {
        int ok64 = 1;
        #pragma unroll 4
        for (int i = 0; i < 2048; i += 2) {
            if (ei_raw[i + 1] != 0) { ok64 = 0; break; }
        }
        g_is64 = ok64;
    }
}

__device__ __forceinline__ int load_idx(const void* ei, long long pos) {
    if (g_is64) return (int)((const long long*)ei)[pos];
    return ((const int*)ei)[pos];
}

// ---------------- graph preprocessing ----------------
__global__ void reset_kernel() {
    int i = blockIdx.x * blockDim.x + threadIdx.x;
    if (i < N_NODES) g_cnt[i] = 0;
}

__global__ void count_kernel(const void* __restrict__ ei) {
    int e = blockIdx.x * blockDim.x + threadIdx.x;
    if (e < N_EDGES) {
        int d = load_idx(ei, (long long)N_EDGES + e);
        if (d >= 0 && d < N_NODES) atomicAdd(&g_cnt[d], 1);
    }
}

// single block, 1024 threads, 4 elems/thread/iter: exclusive scan of g_cnt
__global__ void scan_kernel() {
    __shared__ int wsum[32];
    __shared__ int s_carry;
    int tid = threadIdx.x;
    int lane = tid & 31;
    int wid = tid >> 5;
    if (tid == 0) s_carry = 0;
    __syncthreads();

    for (int base = 0; base < N_NODES; base += 4096) {
        int i0 = base + tid * 4;
        int v0 = (i0 + 0 < N_NODES) ? g_cnt[i0 + 0] : 0;
        int v1 = (i0 + 1 < N_NODES) ? g_cnt[i0 + 1] : 0;
        int v2 = (i0 + 2 < N_NODES) ? g_cnt[i0 + 2] : 0;
        int v3 = (i0 + 3 < N_NODES) ? g_cnt[i0 + 3] : 0;
        int t = v0 + v1 + v2 + v3;

        // warp inclusive scan of t
        int x = t;
        #pragma unroll
        for (int off = 1; off < 32; off <<= 1) {
            int y = __shfl_up_sync(0xffffffffu, x, off);
            if (lane >= off) x += y;
        }
        if (lane == 31) wsum[wid] = x;
        __syncthreads();
        if (wid == 0) {
            int w = wsum[lane];
            #pragma unroll
            for (int off = 1; off < 32; off <<= 1) {
                int y = __shfl_up_sync(0xffffffffu, w, off);
                if (lane >= off) w += y;
            }
            wsum[lane] = w;
        }
        __syncthreads();

        int carry = s_carry;
        int run = carry + (wid ? wsum[wid - 1] : 0) + (x - t);
        if (i0 + 0 < N_NODES) { g_rowstart[i0+0] = run; g_cursor[i0+0] = run; g_invs[i0+0] = rsqrtf((float)(v0 + 1)); run += v0; }
        if (i0 + 1 < N_NODES) { g_rowstart[i0+1] = run; g_cursor[i0+1] = run; g_invs[i0+1] = rsqrtf((float)(v1 + 1)); run += v1; }
        if (i0 + 2 < N_NODES) { g_rowstart[i0+2] = run; g_cursor[i0+2] = run; g_invs[i0+2] = rsqrtf((float)(v2 + 1)); run += v2; }
        if (i0 + 3 < N_NODES) { g_rowstart[i0+3] = run; g_cursor[i0+3] = run; g_invs[i0+3] = rsqrtf((float)(v3 + 1)); run += v3; }
        __syncthreads();                       // everyone has read s_carry / wsum
        if (tid == 0) s_carry = carry + wsum[31];
        __syncthreads();                       // publish before wsum is reused
    }
    if (threadIdx.x == 0) g_rowstart[N_NODES] = s_carry;
}

__global__ void build_kernel(const void* __restrict__ ei) {
    int e = blockIdx.x * blockDim.x + threadIdx.x;
    if (e < N_EDGES) {
        int s = load_idx(ei, e);
        int d = load_idx(ei, (long long)N_EDGES + e);
        if (s >= 0 && s < N_NODES && d >= 0 && d < N_NODES) {
            int p = atomicAdd(&g_cursor[d], 1);
            if (p >= 0 && p < N_EDGES) g_srcSorted[p] = s;
        }
    }
}

// ---------------- GEMM: Y[row] = (scale?) * (X[row] @ W) (+bias?) ----------------
// Block: 256 threads, 128-row x COLS-col tile, 8x(TN) register tile per thread.
// K = 128 always, staged in 32-wide chunks.
template <int COLS, bool XEXT, bool SCALE, bool BIAS, bool YOUT>
__global__ __launch_bounds__(256) void gemm_kernel(
    const float* __restrict__ Xext, const float* __restrict__ W,
    const float* __restrict__ bias, float* __restrict__ Yout)
{
    constexpr int TN = COLS / 16;  // 8 for COLS=128, 4 for COLS=64
    __shared__ float Xs[128][36];          // [row][k-in-chunk], padded
    __shared__ float Ws[32][COLS];         // [k-in-chunk][col]

    const float* X = XEXT ? Xext : g_H;
    float*       Y = YOUT ? Yout : g_U;

    int tid = threadIdx.x;
    int tx = tid & 15;        // col group
    int ty = tid >> 4;        // row group (16 groups of 8 rows)
    int r0 = blockIdx.x * 128;

    float acc[8][TN];
    #pragma unroll
    for (int r = 0; r < 8; r++)
        #pragma unroll
        for (int c = 0; c < TN; c++) acc[r][c] = 0.0f;

    for (int kc = 0; kc < 128; kc += 32) {
        // stage X tile: 128 rows x 32 k  (1024 float4, 4 per thread)
        #pragma unroll
        for (int i = 0; i < 4; i++) {
            int m = tid + 256 * i;
            int row = m >> 3, kq = m & 7;
            float4 v = make_float4(0.f, 0.f, 0.f, 0.f);
            if (r0 + row < N_NODES)
                v = *(const float4*)&X[(size_t)(r0 + row) * 128 + kc + kq * 4];
            *(float4*)&Xs[row][kq * 4] = v;
        }
        // stage W chunk: 32 x COLS
        constexpr int WF4 = 32 * COLS / 4;
        #pragma unroll
        for (int i = 0; i < WF4 / 256; i++) {
            int m = tid + 256 * i;
            int krow = m / (COLS / 4), cq = m % (COLS / 4);
            *(float4*)&Ws[krow][cq * 4] = *(const float4*)&W[(size_t)(kc + krow) * COLS + cq * 4];
        }
        __syncthreads();

        #pragma unroll 8
        for (int k = 0; k < 32; k++) {
            float xr[8];
            #pragma unroll
            for (int r = 0; r < 8; r++) xr[r] = Xs[ty * 8 + r][k];
            float wv[TN];
            *(float4*)&wv[0] = *(const float4*)&Ws[k][tx * 4];
            if (TN == 8)
                *(float4*)&wv[4] = *(const float4*)&Ws[k][64 + tx * 4];
            #pragma unroll
            for (int r = 0; r < 8; r++)
                #pragma unroll
                for (int c = 0; c < TN; c++)
                    acc[r][c] = fmaf(xr[r], wv[c], acc[r][c]);
        }
        __syncthreads();
    }

    // epilogue
    float bv[TN];
    if (BIAS) {
        *(float4*)&bv[0] = *(const float4*)&bias[tx * 4];
        if (TN == 8) *(float4*)&bv[4] = *(const float4*)&bias[64 + tx * 4];
    } else {
        #pragma unroll
        for (int c = 0; c < TN; c++) bv[c] = 0.0f;
    }

    #pragma unroll
    for (int r = 0; r < 8; r++) {
        int row = r0 + ty * 8 + r;
        if (row < N_NODES) {
            float s = SCALE ? g_invs[row] : 1.0f;
            float4 o0;
            o0.x = acc[r][0] * s + bv[0];
            o0.y = acc[r][1] * s + bv[1];
            o0.z = acc[r][2] * s + bv[2];
            o0.w = acc[r][3] * s + bv[3];
            *(float4*)&Y[(size_t)row * COLS + tx * 4] = o0;
            if (TN == 8) {
                float4 o1;
                o1.x = acc[r][4] * s + bv[4];
                o1.y = acc[r][5] * s + bv[5];
                o1.z = acc[r][6] * s + bv[6];
                o1.w = acc[r][7] * s + bv[7];
                *(float4*)&Y[(size_t)row * COLS + 64 + tx * 4] = o1;
            }
        }
    }
}

// ---------------- aggregation: warp per node, pull over CSR ----------------
// H[d] = act( inv_sqrt[d] * (U[d] + sum_{src in N(d)} U[src]) + b )
template <bool RELU>
__global__ __launch_bounds__(256) void agg_kernel(const float* __restrict__ bias) {
    int gw = (blockIdx.x * 256 + threadIdx.x) >> 5;  // node id
    int lane = threadIdx.x & 31;
    if (gw >= N_NODES) return;

    const float4* Up = (const float4*)g_U;
    float4 a = Up[(size_t)gw * 32 + lane];           // self-loop term
    int beg = g_rowstart[gw];
    int end = g_rowstart[gw + 1];

    int j = beg;
    for (; j + 4 <= end; j += 4) {
        int s0 = g_srcSorted[j + 0];
        int s1 = g_srcSorted[j + 1];
        int s2 = g_srcSorted[j + 2];
        int s3 = g_srcSorted[j + 3];
        float4 v0 = Up[(size_t)s0 * 32 + lane];
        float4 v1 = Up[(size_t)s1 * 32 + lane];
        float4 v2 = Up[(size_t)s2 * 32 + lane];
        float4 v3 = Up[(size_t)s3 * 32 + lane];
        a.x += (v0.x + v1.x) + (v2.x + v3.x);
        a.y += (v0.y + v1.y) + (v2.y + v3.y);
        a.z += (v0.z + v1.z) + (v2.z + v3.z);
        a.w += (v0.w + v1.w) + (v2.w + v3.w);
    }
    for (; j < end; j++) {
        int s = g_srcSorted[j];
        float4 v = Up[(size_t)s * 32 + lane];
        a.x += v.x; a.y += v.y; a.z += v.z; a.w += v.w;
    }

    float is = g_invs[gw];
    float4 b4 = ((const float4*)bias)[lane];
    float4 o;
    o.x = is * a.x + b4.x;
    o.y = is * a.y + b4.y;
    o.z = is * a.z + b4.z;
    o.w = is * a.w + b4.w;
    if (RELU) {
        o.x = fmaxf(o.x, 0.f);
        o.y = fmaxf(o.y, 0.f);
        o.z = fmaxf(o.z, 0.f);
        o.w = fmaxf(o.w, 0.f);
    }
    ((float4*)g_H)[(size_t)gw * 32 + lane] = o;
}

// ---------------- launch ----------------
extern "C" void kernel_launch(void* const* d_in, const int* in_sizes, int n_in,
                              void* d_out, int out_size)
{
    const float* x  = (const float*)d_in[0];
    const void*  ei = d_in[1];
    const float* W1 = (const float*)d_in[2];
    const float* b1 = (const float*)d_in[3];
    const float* W2 = (const float*)d_in[4];
    const float* b2 = (const float*)d_in[5];
    const float* W3 = (const float*)d_in[6];
    const float* b3 = (const float*)d_in[7];
    const float* Wo = (const float*)d_in[8];
    const float* bo = (const float*)d_in[9];
    float* out = (float*)d_out;

    // graph preprocessing (rebuilt every call; graph-replay deterministic)
    detect_kernel<<<1, 32>>>((const int*)ei);
    reset_kernel<<<(N_NODES + 255) / 256, 256>>>();
    count_kernel<<<(N_EDGES + 255) / 256, 256>>>(ei);
    scan_kernel<<<1, 1024>>>();
    build_kernel<<<(N_EDGES + 255) / 256, 256>>>(ei);

    const int GB = (N_NODES + 127) / 128;
    const int AB = (N_NODES + 7) / 8;

    // layer 1: u = invs*(x@W1); h = relu(invs*(agg)+b1)
    gemm_kernel<128, true,  true,  false, false><<<GB, 256>>>(x, W1, nullptr, nullptr);
    agg_kernel<true><<<AB, 256>>>(b1);
    // layer 2
    gemm_kernel<128, false, true,  false, false><<<GB, 256>>>(nullptr, W2, nullptr, nullptr);
    agg_kernel<true><<<AB, 256>>>(b2);
    // layer 3 (no relu)
    gemm_kernel<128, false, true,  false, false><<<GB, 256>>>(nullptr, W3, nullptr, nullptr);
    agg_kernel<false><<<AB, 256>>>(b3);
    // output projection: out = h @ Wout + bout
    gemm_kernel<64,  false, false, true,  true ><<<GB, 256>>>(nullptr, Wo, bo, out);
}

// round 4
// speedup vs baseline: 1.1693x; 1.1693x over previous
#include <cuda_runtime.h>
#include <math.h>

#define N_NODES 100000
#define N_EDGES 1600000
#define F       128
#define OUTC    64
#define SCAN_CHUNK 4096
#define SCAN_NB ((N_NODES + SCAN_CHUNK - 1) / SCAN_CHUNK)   // 25

// ---------------- scratch (static device globals; no allocation) ----------------
__device__ float g_U[(size_t)N_NODES * F];     // u = inv_sqrt * (h @ W)
__device__ float g_H[(size_t)N_NODES * F];     // layer activations
__device__ int   g_srcSorted[N_EDGES];         // CSR: src indices grouped by dst
__device__ int   g_cnt[N_NODES];               // in-degree (edges only)
__device__ int   g_rowstart[N_NODES + 1];      // CSR row offsets
__device__ int   g_cursor[N_NODES];            // scatter cursors
__device__ float g_invs[N_NODES];              // deg^{-1/2}, deg = cnt+1 (self loop)
__device__ int   g_is64;                       // edge_index dtype flag
__device__ int   g_bsum[SCAN_NB];              // per-block scan totals
__device__ int   g_boff[SCAN_NB];              // per-block exclusive offsets
__device__ int   g_total;

// ---------------- dtype probe ----------------
__global__ void detect_kernel(const int* __restrict__ ei_raw) {
    if (blockIdx.x == 0 && threadIdx.x == 0) {
        int ok64 = 1;
        #pragma unroll 4
        for (int i = 0; i < 2048; i += 2) {
            if (ei_raw[i + 1] != 0) { ok64 = 0; break; }
        }
        g_is64 = ok64;
    }
}

__device__ __forceinline__ int load_idx(const void* ei, long long pos) {
    if (g_is64) return (int)((const long long*)ei)[pos];
    return ((const int*)ei)[pos];
}

// ---------------- graph preprocessing ----------------
__global__ void reset_kernel() {
    int i = blockIdx.x * blockDim.x + threadIdx.x;
    if (i < N_NODES) g_cnt[i] = 0;
}

__global__ void count_kernel(const void* __restrict__ ei) {
    int e = blockIdx.x * blockDim.x + threadIdx.x;
    if (e < N_EDGES) {
        int d = load_idx(ei, (long long)N_EDGES + e);
        if (d >= 0 && d < N_NODES) atomicAdd(&g_cnt[d], 1);
    }
}

// Phase 1: per-block local exclusive scan of g_cnt into g_rowstart; block total to g_bsum.
__global__ __launch_bounds__(1024) void scan_local_kernel() {
    __shared__ int wsum[32];
    int tid = threadIdx.x, lane = tid & 31, wid = tid >> 5;
    int i0 = blockIdx.x * SCAN_CHUNK + tid * 4;

    int v0 = (i0 + 0 < N_NODES) ? g_cnt[i0 + 0] : 0;
    int v1 = (i0 + 1 < N_NODES) ? g_cnt[i0 + 1] : 0;
    int v2 = (i0 + 2 < N_NODES) ? g_cnt[i0 + 2] : 0;
    int v3 = (i0 + 3 < N_NODES) ? g_cnt[i0 + 3] : 0;
    int t = v0 + v1 + v2 + v3;

    int x = t;
    #pragma unroll
    for (int off = 1; off < 32; off <<= 1) {
        int y = __shfl_up_sync(0xffffffffu, x, off);
        if (lane >= off) x += y;
    }
    if (lane == 31) wsum[wid] = x;
    __syncthreads();
    if (wid == 0) {
        int w = wsum[lane];
        #pragma unroll
        for (int off = 1; off < 32; off <<= 1) {
            int y = __shfl_up_sync(0xffffffffu, w, off);
            if (lane >= off) w += y;
        }
        wsum[lane] = w;
    }
    __syncthreads();

    int run = (wid ? wsum[wid - 1] : 0) + (x - t);  // exclusive prefix in block
    if (i0 + 0 < N_NODES) { g_rowstart[i0+0] = run; run += v0; }
    if (i0 + 1 < N_NODES) { g_rowstart[i0+1] = run; run += v1; }
    if (i0 + 2 < N_NODES) { g_rowstart[i0+2] = run; run += v2; }
    if (i0 + 3 < N_NODES) { g_rowstart[i0+3] = run; run += v3; }
    if (tid == 0) g_bsum[blockIdx.x] = wsum[31];
}

// Phase 2: one warp scans the 25 block sums.
__global__ void scan_bsums_kernel() {
    int lane = threadIdx.x;
    int v = (lane < SCAN_NB) ? g_bsum[lane] : 0;
    int x = v;
    #pragma unroll
    for (int off = 1; off < 32; off <<= 1) {
        int y = __shfl_up_sync(0xffffffffu, x, off);
        if (lane >= off) x += y;
    }
    if (lane < SCAN_NB) g_boff[lane] = x - v;
    if (lane == 31) g_total = x;
}

// Phase 3: add block offsets; emit rowstart/cursor/invs.
__global__ void scan_finalize_kernel() {
    int i = blockIdx.x * blockDim.x + threadIdx.x;
    if (i < N_NODES) {
        int v = g_rowstart[i] + g_boff[i >> 12];   // 4096 = 2^12
        g_rowstart[i] = v;
        g_cursor[i] = v;
        g_invs[i] = rsqrtf((float)(g_cnt[i] + 1));
    }
    if (i == 0) g_rowstart[N_NODES] = g_total;
}

__global__ void build_kernel(const void* __restrict__ ei) {
    int e = blockIdx.x * blockDim.x + threadIdx.x;
    if (e < N_EDGES) {
        int s = load_idx(ei, e);
        int d = load_idx(ei, (long long)N_EDGES + e);
        if (s >= 0 && s < N_NODES && d >= 0 && d < N_NODES) {
            int p = atomicAdd(&g_cursor[d], 1);
            if (p >= 0 && p < N_EDGES) g_srcSorted[p] = s;
        }
    }
}

// ---------------- GEMM: Y[row] = (scale?) * (X[row] @ W) (+bias?) ----------------
template <int COLS, bool XEXT, bool SCALE, bool BIAS, bool YOUT>
__global__ __launch_bounds__(256, 2) void gemm_kernel(
    const float* __restrict__ Xext, const float* __restrict__ W,
    const float* __restrict__ bias, float* __restrict__ Yout)
{
    constexpr int TN = COLS / 16;  // 8 for COLS=128, 4 for COLS=64
    __shared__ float Xs[128][36];          // [row][k-in-chunk], padded (36*4=144B rows, 8B aligned)
    __shared__ float Ws[32][COLS];         // [k-in-chunk][col]

    const float* X = XEXT ? Xext : g_H;
    float*       Y = YOUT ? Yout : g_U;

    int tid = threadIdx.x;
    int tx = tid & 15;        // col group
    int ty = tid >> 4;        // row group (16 groups of 8 rows)
    int r0 = blockIdx.x * 128;

    float acc[8][TN];
    #pragma unroll
    for (int r = 0; r < 8; r++)
        #pragma unroll
        for (int c = 0; c < TN; c++) acc[r][c] = 0.0f;

    for (int kc = 0; kc < 128; kc += 32) {
        // stage X tile: 128 rows x 32 k  (1024 float4, 4 per thread)
        #pragma unroll
        for (int i = 0; i < 4; i++) {
            int m = tid + 256 * i;
            int row = m >> 3, kq = m & 7;
            float4 v = make_float4(0.f, 0.f, 0.f, 0.f);
            if (r0 + row < N_NODES)
                v = *(const float4*)&X[(size_t)(r0 + row) * 128 + kc + kq * 4];
            *(float4*)&Xs[row][kq * 4] = v;
        }
        // stage W chunk: 32 x COLS
        constexpr int WF4 = 32 * COLS / 4;
        #pragma unroll
        for (int i = 0; i < WF4 / 256; i++) {
            int m = tid + 256 * i;
            int krow = m / (COLS / 4), cq = m % (COLS / 4);
            *(float4*)&Ws[krow][cq * 4] = *(const float4*)&W[(size_t)(kc + krow) * COLS + cq * 4];
        }
        __syncthreads();

        // inner loop: 2 k's per step; float2 x-fragments, float4 w-fragments
        #pragma unroll
        for (int k0 = 0; k0 < 32; k0 += 2) {
            float2 xr[8];
            #pragma unroll
            for (int r = 0; r < 8; r++)
                xr[r] = *(const float2*)&Xs[ty * 8 + r][k0];

            float w0[TN], w1[TN];
            *(float4*)&w0[0] = *(const float4*)&Ws[k0][tx * 4];
            *(float4*)&w1[0] = *(const float4*)&Ws[k0 + 1][tx * 4];
            if (TN == 8) {
                *(float4*)&w0[4] = *(const float4*)&Ws[k0][64 + tx * 4];
                *(float4*)&w1[4] = *(const float4*)&Ws[k0 + 1][64 + tx * 4];
            }
            #pragma unroll
            for (int r = 0; r < 8; r++)
                #pragma unroll
                for (int c = 0; c < TN; c++) {
                    acc[r][c] = fmaf(xr[r].x, w0[c], acc[r][c]);
                    acc[r][c] = fmaf(xr[r].y, w1[c], acc[r][c]);
                }
        }
        __syncthreads();
    }

    // epilogue
    float bv[TN];
    if (BIAS) {
        *(float4*)&bv[0] = *(const float4*)&bias[tx * 4];
        if (TN == 8) *(float4*)&bv[4] = *(const float4*)&bias[64 + tx * 4];
    } else {
        #pragma unroll
        for (int c = 0; c < TN; c++) bv[c] = 0.0f;
    }

    #pragma unroll
    for (int r = 0; r < 8; r++) {
        int row = r0 + ty * 8 + r;
        if (row < N_NODES) {
            float s = SCALE ? g_invs[row] : 1.0f;
            float4 o0;
            o0.x = acc[r][0] * s + bv[0];
            o0.y = acc[r][1] * s + bv[1];
            o0.z = acc[r][2] * s + bv[2];
            o0.w = acc[r][3] * s + bv[3];
            *(float4*)&Y[(size_t)row * COLS + tx * 4] = o0;
            if (TN == 8) {
                float4 o1;
                o1.x = acc[r][4] * s + bv[4];
                o1.y = acc[r][5] * s + bv[5];
                o1.z = acc[r][6] * s + bv[6];
                o1.w = acc[r][7] * s + bv[7];
                *(float4*)&Y[(size_t)row * COLS + 64 + tx * 4] = o1;
            }
        }
    }
}

// ---------------- aggregation: warp per node, pull over CSR ----------------
template <bool RELU>
__global__ __launch_bounds__(256) void agg_kernel(const float* __restrict__ bias) {
    int gw = (blockIdx.x * 256 + threadIdx.x) >> 5;  // node id
    int lane = threadIdx.x & 31;
    if (gw >= N_NODES) return;

    const float4* Up = (const float4*)g_U;
    float4 a = Up[(size_t)gw * 32 + lane];           // self-loop term
    int beg = g_rowstart[gw];
    int end = g_rowstart[gw + 1];

    int j = beg;
    for (; j + 4 <= end; j += 4) {
        int s0 = g_srcSorted[j + 0];
        int s1 = g_srcSorted[j + 1];
        int s2 = g_srcSorted[j + 2];
        int s3 = g_srcSorted[j + 3];
        float4 v0 = Up[(size_t)s0 * 32 + lane];
        float4 v1 = Up[(size_t)s1 * 32 + lane];
        float4 v2 = Up[(size_t)s2 * 32 + lane];
        float4 v3 = Up[(size_t)s3 * 32 + lane];
        a.x += (v0.x + v1.x) + (v2.x + v3.x);
        a.y += (v0.y + v1.y) + (v2.y + v3.y);
        a.z += (v0.z + v1.z) + (v2.z + v3.z);
        a.w += (v0.w + v1.w) + (v2.w + v3.w);
    }
    for (; j < end; j++) {
        int s = g_srcSorted[j];
        float4 v = Up[(size_t)s * 32 + lane];
        a.x += v.x; a.y += v.y; a.z += v.z; a.w += v.w;
    }

    float is = g_invs[gw];
    float4 b4 = ((const float4*)bias)[lane];
    float4 o;
    o.x = is * a.x + b4.x;
    o.y = is * a.y + b4.y;
    o.z = is * a.z + b4.z;
    o.w = is * a.w + b4.w;
    if (RELU) {
        o.x = fmaxf(o.x, 0.f);
        o.y = fmaxf(o.y, 0.f);
        o.z = fmaxf(o.z, 0.f);
        o.w = fmaxf(o.w, 0.f);
    }
    ((float4*)g_H)[(size_t)gw * 32 + lane] = o;
}

// ---------------- launch ----------------
extern "C" void kernel_launch(void* const* d_in, const int* in_sizes, int n_in,
                              void* d_out, int out_size)
{
    const float* x  = (const float*)d_in[0];
    const void*  ei = d_in[1];
    const float* W1 = (const float*)d_in[2];
    const float* b1 = (const float*)d_in[3];
    const float* W2 = (const float*)d_in[4];
    const float* b2 = (const float*)d_in[5];
    const float* W3 = (const float*)d_in[6];
    const float* b3 = (const float*)d_in[7];
    const float* Wo = (const float*)d_in[8];
    const float* bo = (const float*)d_in[9];
    float* out = (float*)d_out;

    // graph preprocessing (rebuilt every call; graph-replay deterministic)
    detect_kernel<<<1, 32>>>((const int*)ei);
    reset_kernel<<<(N_NODES + 255) / 256, 256>>>();
    count_kernel<<<(N_EDGES + 255) / 256, 256>>>(ei);
    scan_local_kernel<<<SCAN_NB, 1024>>>();
    scan_bsums_kernel<<<1, 32>>>();
    scan_finalize_kernel<<<(N_NODES + 255) / 256, 256>>>();
    build_kernel<<<(N_EDGES + 255) / 256, 256>>>(ei);

    const int GB = (N_NODES + 127) / 128;
    const int AB = (N_NODES + 7) / 8;

    // layer 1: u = invs*(x@W1); h = relu(invs*(agg)+b1)
    gemm_kernel<128, true,  true,  false, false><<<GB, 256>>>(x, W1, nullptr, nullptr);
    agg_kernel<true><<<AB, 256>>>(b1);
    // layer 2
    gemm_kernel<128, false, true,  false, false><<<GB, 256>>>(nullptr, W2, nullptr, nullptr);
    agg_kernel<true><<<AB, 256>>>(b2);
    // layer 3 (no relu)
    gemm_kernel<128, false, true,  false, false><<<GB, 256>>>(nullptr, W3, nullptr, nullptr);
    agg_kernel<false><<<AB, 256>>>(b3);
    // output projection: out = h @ Wout + bout
    gemm_kernel<64,  false, false, true,  true ><<<GB, 256>>>(nullptr, Wo, bo, out);
}

// round 6
// speedup vs baseline: 1.5301x; 1.3086x over previous
#include <cuda_runtime.h>
#include <cuda_bf16.h>
#include <math.h>
#include <stdint.h>

#define N_NODES 100000
#define N_EDGES 1600000
#define NBLK    ((N_NODES + 127) / 128)      // 782
#define SCAN_CHUNK 4096
#define SCAN_NB ((N_NODES + SCAN_CHUNK - 1) / SCAN_CHUNK)   // 25
#define PAD 136   // bf16 elems per SMEM row: 272B stride -> conflict-free ldmatrix

// ---------------- scratch (static device globals; no allocation) ----------------
__device__ float g_U[(size_t)N_NODES * 128];   // u = inv_sqrt * (h @ W)
__device__ float g_H[(size_t)N_NODES * 128];   // layer activations
__device__ __nv_bfloat16 g_Wbf[114688];        // W images [n][k], hi+lo per layer
__device__ int   g_srcSorted[N_EDGES];
__device__ int   g_cnt[N_NODES];
__device__ int   g_rowstart[N_NODES + 1];
__device__ int   g_cursor[N_NODES];
__device__ float g_invs[N_NODES];
__device__ int   g_is64;
__device__ int   g_bsum[SCAN_NB];
__device__ int   g_boff[SCAN_NB];
__device__ int   g_total;

// W image element offsets (in g_Wbf)
#define W1_HI 0
#define W1_LO 16384
#define W2_HI 32768
#define W2_LO 49152
#define W3_HI 65536
#define W3_LO 81920
#define WO_HI 98304
#define WO_LO 106496

// ---------------- mma helpers ----------------
__device__ __forceinline__ void ldsm4(uint32_t* r, const __nv_bfloat16* p) {
    uint32_t a = (uint32_t)__cvta_generic_to_shared(p);
    asm volatile("ldmatrix.sync.aligned.m8n8.x4.shared.b16 {%0,%1,%2,%3}, [%4];"
                 : "=r"(r[0]), "=r"(r[1]), "=r"(r[2]), "=r"(r[3]) : "r"(a));
}

__device__ __forceinline__ void mma16816(float* c, const uint32_t* a, const uint32_t* b) {
    asm volatile(
        "mma.sync.aligned.m16n8k16.row.col.f32.bf16.bf16.f32 "
        "{%0,%1,%2,%3}, {%4,%5,%6,%7}, {%8,%9}, {%0,%1,%2,%3};"
        : "+f"(c[0]), "+f"(c[1]), "+f"(c[2]), "+f"(c[3])
        : "r"(a[0]), "r"(a[1]), "r"(a[2]), "r"(a[3]), "r"(b[0]), "r"(b[1]));
}

// ---------------- dtype probe ----------------
__global__ void detect_kernel(const int* __restrict__ ei_raw) {
    if (blockIdx.x == 0 && threadIdx.x == 0) {
        int ok64 = 1;
        #pragma unroll 4
        for (int i = 0; i < 2048; i += 2)
            if (ei_raw[i + 1] != 0) { ok64 = 0; break; }
        g_is64 = ok64;
    }
}

__device__ __forceinline__ int load_idx(const void* ei, long long pos) {
    if (g_is64) return (int)((const long long*)ei)[pos];
    return ((const int*)ei)[pos];
}

// ---------------- graph preprocessing ----------------
__global__ void reset_kernel() {
    int i = blockIdx.x * blockDim.x + threadIdx.x;
    if (i < N_NODES) g_cnt[i] = 0;
}

__global__ void count_kernel(const void* __restrict__ ei) {
    int e = blockIdx.x * blockDim.x + threadIdx.x;
    if (e < N_EDGES) {
        int d = load_idx(ei, (long long)N_EDGES + e);
        if (d >= 0 && d < N_NODES) atomicAdd(&g_cnt[d], 1);
    }
}

__global__ __launch_bounds__(1024) void scan_local_kernel() {
    __shared__ int wsum[32];
    int tid = threadIdx.x, lane = tid & 31, wid = tid >> 5;
    int i0 = blockIdx.x * SCAN_CHUNK + tid * 4;

    int v0 = (i0 + 0 < N_NODES) ? g_cnt[i0 + 0] : 0;
    int v1 = (i0 + 1 < N_NODES) ? g_cnt[i0 + 1] : 0;
    int v2 = (i0 + 2 < N_NODES) ? g_cnt[i0 + 2] : 0;
    int v3 = (i0 + 3 < N_NODES) ? g_cnt[i0 + 3] : 0;
    int t = v0 + v1 + v2 + v3;

    int x = t;
    #pragma unroll
    for (int off = 1; off < 32; off <<= 1) {
        int y = __shfl_up_sync(0xffffffffu, x, off);
        if (lane >= off) x += y;
    }
    if (lane == 31) wsum[wid] = x;
    __syncthreads();
    if (wid == 0) {
        int w = wsum[lane];
        #pragma unroll
        for (int off = 1; off < 32; off <<= 1) {
            int y = __shfl_up_sync(0xffffffffu, w, off);
            if (lane >= off) w += y;
        }
        wsum[lane] = w;
    }
    __syncthreads();

    int run = (wid ? wsum[wid - 1] : 0) + (x - t);
    if (i0 + 0 < N_NODES) { g_rowstart[i0+0] = run; run += v0; }
    if (i0 + 1 < N_NODES) { g_rowstart[i0+1] = run; run += v1; }
    if (i0 + 2 < N_NODES) { g_rowstart[i0+2] = run; run += v2; }
    if (i0 + 3 < N_NODES) { g_rowstart[i0+3] = run; run += v3; }
    if (tid == 0) g_bsum[blockIdx.x] = wsum[31];
}

__global__ void scan_bsums_kernel() {
    int lane = threadIdx.x;
    int v = (lane < SCAN_NB) ? g_bsum[lane] : 0;
    int x = v;
    #pragma unroll
    for (int off = 1; off < 32; off <<= 1) {
        int y = __shfl_up_sync(0xffffffffu, x, off);
        if (lane >= off) x += y;
    }
    if (lane < SCAN_NB) g_boff[lane] = x - v;
    if (lane == 31) g_total = x;
}

__global__ void scan_finalize_kernel() {
    int i = blockIdx.x * blockDim.x + threadIdx.x;
    if (i < N_NODES) {
        int v = g_rowstart[i] + g_boff[i >> 12];
        g_rowstart[i] = v;
        g_cursor[i] = v;
        g_invs[i] = rsqrtf((float)(g_cnt[i] + 1));
    }
    if (i == 0) g_rowstart[N_NODES] = g_total;
}

__global__ void build_kernel(const void* __restrict__ ei) {
    int e = blockIdx.x * blockDim.x + threadIdx.x;
    if (e < N_EDGES) {
        int s = load_idx(ei, e);
        int d = load_idx(ei, (long long)N_EDGES + e);
        if (s >= 0 && s < N_NODES && d >= 0 && d < N_NODES) {
            int p = atomicAdd(&g_cursor[d], 1);
            if (p >= 0 && p < N_EDGES) g_srcSorted[p] = s;
        }
    }
}

// ---------------- weight image prep: [k][n] fp32 -> [n][k] bf16 hi/lo ----------------
__global__ void prep_w_kernel(const float* __restrict__ W, int N, int off_hi, int off_lo) {
    int e = blockIdx.x * blockDim.x + threadIdx.x;
    if (e >= 128 * N) return;
    int k = e / N, n = e % N;
    float v = W[e];
    __nv_bfloat16 hb = __float2bfloat16(v);
    __nv_bfloat16 lb = __float2bfloat16(v - __bfloat162float(hb));
    g_Wbf[off_hi + n * 128 + k] = hb;
    g_Wbf[off_lo + n * 128 + k] = lb;
}

// ---------------- tensor-core GEMM (mma.sync bf16, split 3-term) ----------------
// D[128, N] = X[128,128] @ W ; per-row scale (invs) and/or bias in epilogue.
template <int N, bool XEXT, bool SCALE, bool BIAS, bool YOUT>
__global__ __launch_bounds__(256) void gemm_mma(
    const float* __restrict__ Xext, int w_hi, int w_lo,
    const float* __restrict__ bias, float* __restrict__ Yout)
{
    extern __shared__ __align__(16) __nv_bfloat16 sm[];
    __nv_bfloat16* Ah = sm;                         // [128][PAD]
    __nv_bfloat16* Al = Ah + 128 * PAD;
    __nv_bfloat16* Bh = Al + 128 * PAD;             // [N][PAD]
    __nv_bfloat16* Bl = Bh + N * PAD;

    const float* X = XEXT ? Xext : g_H;
    float* Y = YOUT ? Yout : g_U;

    int tid = threadIdx.x;
    int lane = tid & 31, warp = tid >> 5;
    int r0 = blockIdx.x * 128;

    // ---- stage A: load fp32, split to bf16 hi/lo ----
    #pragma unroll
    for (int i = 0; i < 16; i++) {
        int j = tid + i * 256;            // 4096 float4 groups
        int row = j >> 5, c4 = (j & 31) << 2;
        float4 v = make_float4(0.f, 0.f, 0.f, 0.f);
        if (r0 + row < N_NODES)
            v = *(const float4*)&X[(size_t)(r0 + row) * 128 + c4];
        float vv[4] = {v.x, v.y, v.z, v.w};
        uint32_t h[4], l[4];
        #pragma unroll
        for (int q = 0; q < 4; q++) {
            __nv_bfloat16 hb = __float2bfloat16(vv[q]);
            h[q] = (uint32_t)__bfloat16_as_ushort(hb);
            l[q] = (uint32_t)__bfloat16_as_ushort(
                       __float2bfloat16(vv[q] - __bfloat162float(hb)));
        }
        *(uint2*)&Ah[row * PAD + c4] = make_uint2(h[0] | (h[1] << 16), h[2] | (h[3] << 16));
        *(uint2*)&Al[row * PAD + c4] = make_uint2(l[0] | (l[1] << 16), l[2] | (l[3] << 16));
    }
    // ---- stage B: copy prepped bf16 images ----
    #pragma unroll
    for (int i = 0; i < N * 16 / 256; i++) {
        int j = tid + i * 256;
        int row = j >> 4, q = j & 15;
        *(uint4*)&Bh[row * PAD + q * 8] = *(const uint4*)&g_Wbf[w_hi + row * 128 + q * 8];
        *(uint4*)&Bl[row * PAD + q * 8] = *(const uint4*)&g_Wbf[w_lo + row * 128 + q * 8];
    }
    __syncthreads();

    // warp layout: 4 (M) x 2 (N); warp tile 32 x (N/2)
    constexpr int NT = N / 16;            // n-tiles (8 wide) per warp: 8 or 4
    int wm = (warp & 3) * 32;
    int wn = (warp >> 2) * (N / 2);

    float acc[2][NT][4];
    #pragma unroll
    for (int mt = 0; mt < 2; mt++)
        #pragma unroll
        for (int nt = 0; nt < NT; nt++)
            #pragma unroll
            for (int q = 0; q < 4; q++) acc[mt][nt][q] = 0.f;

    int arow = lane & 15, acol = (lane >> 4) << 3;
    int brow = (lane & 7) + ((lane >> 4) << 3), bcol = ((lane >> 3) & 1) << 3;

    #pragma unroll
    for (int kk = 0; kk < 128; kk += 16) {
        uint32_t ah[2][4], al[2][4];
        ldsm4(ah[0], Ah + (wm + arow) * PAD + kk + acol);
        ldsm4(ah[1], Ah + (wm + 16 + arow) * PAD + kk + acol);
        ldsm4(al[0], Al + (wm + arow) * PAD + kk + acol);
        ldsm4(al[1], Al + (wm + 16 + arow) * PAD + kk + acol);

        uint32_t bh[NT][2], bl[NT][2];
        #pragma unroll
        for (int p = 0; p < NT / 2; p++) {
            uint32_t t[4];
            const __nv_bfloat16* pb = Bh + (wn + p * 16 + brow) * PAD + kk + bcol;
            ldsm4(t, pb);
            bh[2*p][0] = t[0]; bh[2*p][1] = t[1];
            bh[2*p+1][0] = t[2]; bh[2*p+1][1] = t[3];
            const __nv_bfloat16* pl = Bl + (wn + p * 16 + brow) * PAD + kk + bcol;
            ldsm4(t, pl);
            bl[2*p][0] = t[0]; bl[2*p][1] = t[1];
            bl[2*p+1][0] = t[2]; bl[2*p+1][1] = t[3];
        }

        #pragma unroll
        for (int mt = 0; mt < 2; mt++)
            #pragma unroll
            for (int nt = 0; nt < NT; nt++) {
                mma16816(acc[mt][nt], ah[mt], bh[nt]);
                mma16816(acc[mt][nt], ah[mt], bl[nt]);
                mma16816(acc[mt][nt], al[mt], bh[nt]);
            }
    }

    // ---- epilogue ----
    #pragma unroll
    for (int mt = 0; mt < 2; mt++) {
        int r1 = r0 + wm + mt * 16 + (lane >> 2);
        int r2 = r1 + 8;
        float s1 = 1.f, s2 = 1.f;
        if (SCALE) {
            if (r1 < N_NODES) s1 = g_invs[r1];
            if (r2 < N_NODES) s2 = g_invs[r2];
        }
        #pragma unroll
        for (int nt = 0; nt < NT; nt++) {
            int col = wn + nt * 8 + ((lane & 3) << 1);
            float bx = 0.f, by = 0.f;
            if (BIAS) { bx = bias[col]; by = bias[col + 1]; }
            if (r1 < N_NODES) {
                float2 o = make_float2(acc[mt][nt][0] * s1 + bx,
                                       acc[mt][nt][1] * s1 + by);
                *(float2*)&Y[(size_t)r1 * N + col] = o;
            }
            if (r2 < N_NODES) {
                float2 o = make_float2(acc[mt][nt][2] * s2 + bx,
                                       acc[mt][nt][3] * s2 + by);
                *(float2*)&Y[(size_t)r2 * N + col] = o;
            }
        }
    }
}

// ---------------- aggregation: warp per node, pull over CSR ----------------
template <bool RELU>
__global__ __launch_bounds__(256) void agg_kernel(const float* __restrict__ bias) {
    int gw = (blockIdx.x * 256 + threadIdx.x) >> 5;
    int lane = threadIdx.x & 31;
    if (gw >= N_NODES) return;

    const float4* Up = (const float4*)g_U;
    float4 a = Up[(size_t)gw * 32 + lane];           // self-loop term
    int beg = g_rowstart[gw];
    int end = g_rowstart[gw + 1];

    int j = beg;
    for (; j + 4 <= end; j += 4) {
        int s0 = g_srcSorted[j + 0];
        int s1 = g_srcSorted[j + 1];
        int s2 = g_srcSorted[j + 2];
        int s3 = g_srcSorted[j + 3];
        float4 v0 = Up[(size_t)s0 * 32 + lane];
        float4 v1 = Up[(size_t)s1 * 32 + lane];
        float4 v2 = Up[(size_t)s2 * 32 + lane];
        float4 v3 = Up[(size_t)s3 * 32 + lane];
        a.x += (v0.x + v1.x) + (v2.x + v3.x);
        a.y += (v0.y + v1.y) + (v2.y + v3.y);
        a.z += (v0.z + v1.z) + (v2.z + v3.z);
        a.w += (v0.w + v1.w) + (v2.w + v3.w);
    }
    for (; j < end; j++) {
        int s = g_srcSorted[j];
        float4 v = Up[(size_t)s * 32 + lane];
        a.x += v.x; a.y += v.y; a.z += v.z; a.w += v.w;
    }

    float is = g_invs[gw];
    float4 b4 = ((const float4*)bias)[lane];
    float4 o;
    o.x = is * a.x + b4.x;
    o.y = is * a.y + b4.y;
    o.z = is * a.z + b4.z;
    o.w = is * a.w + b4.w;
    if (RELU) {
        o.x = fmaxf(o.x, 0.f);
        o.y = fmaxf(o.y, 0.f);
        o.z = fmaxf(o.z, 0.f);
        o.w = fmaxf(o.w, 0.f);
    }
    ((float4*)g_H)[(size_t)gw * 32 + lane] = o;
}

// ---------------- launch ----------------
extern "C" void kernel_launch(void* const* d_in, const int* in_sizes, int n_in,
                              void* d_out, int out_size)
{
    const float* x  = (const float*)d_in[0];
    const void*  ei = d_in[1];
    const float* W1 = (const float*)d_in[2];
    const float* b1 = (const float*)d_in[3];
    const float* W2 = (const float*)d_in[4];
    const float* b2 = (const float*)d_in[5];
    const float* W3 = (const float*)d_in[6];
    const float* b3 = (const float*)d_in[7];
    const float* Wo = (const float*)d_in[8];
    const float* bo = (const float*)d_in[9];
    float* out = (float*)d_out;

    const int SMEM128 = (2 * 128 * PAD + 2 * 128 * PAD) * 2;  // 139264 B
    const int SMEM64  = (2 * 128 * PAD + 2 * 64  * PAD) * 2;  // 104448 B
    cudaFuncSetAttribute(gemm_mma<128, true,  true,  false, false>,
                         cudaFuncAttributeMaxDynamicSharedMemorySize, SMEM128);
    cudaFuncSetAttribute(gemm_mma<128, false, true,  false, false>,
                         cudaFuncAttributeMaxDynamicSharedMemorySize, SMEM128);
    cudaFuncSetAttribute(gemm_mma<64,  false, false, true,  true>,
                         cudaFuncAttributeMaxDynamicSharedMemorySize, SMEM64);

    // graph preprocessing
    detect_kernel<<<1, 32>>>((const int*)ei);
    reset_kernel<<<(N_NODES + 255) / 256, 256>>>();
    count_kernel<<<(N_EDGES + 255) / 256, 256>>>(ei);
    scan_local_kernel<<<SCAN_NB, 1024>>>();
    scan_bsums_kernel<<<1, 32>>>();
    scan_finalize_kernel<<<(N_NODES + 255) / 256, 256>>>();
    build_kernel<<<(N_EDGES + 255) / 256, 256>>>(ei);

    // weight images
    prep_w_kernel<<<64, 256>>>(W1, 128, W1_HI, W1_LO);
    prep_w_kernel<<<64, 256>>>(W2, 128, W2_HI, W2_LO);
    prep_w_kernel<<<64, 256>>>(W3, 128, W3_HI, W3_LO);
    prep_w_kernel<<<32, 256>>>(Wo, 64,  WO_HI, WO_LO);

    const int AB = (N_NODES + 7) / 8;

    // layer 1
    gemm_mma<128, true,  true,  false, false><<<NBLK, 256, SMEM128>>>(x, W1_HI, W1_LO, nullptr, nullptr);
    agg_kernel<true><<<AB, 256>>>(b1);
    // layer 2
    gemm_mma<128, false, true,  false, false><<<NBLK, 256, SMEM128>>>(nullptr, W2_HI, W2_LO, nullptr, nullptr);
    agg_kernel<true><<<AB, 256>>>(b2);
    // layer 3 (no relu)
    gemm_mma<128, false, true,  false, false><<<NBLK, 256, SMEM128>>>(nullptr, W3_HI, W3_LO, nullptr, nullptr);
    agg_kernel<false><<<AB, 256>>>(b3);
    // output projection
    gemm_mma<64, false, false, true, true><<<NBLK, 256, SMEM64>>>(nullptr, WO_HI, WO_LO, bo, out);
}

// round 7
// speedup vs baseline: 1.7048x; 1.1142x over previous
#include <cuda_runtime.h>
#include <cuda_bf16.h>
#include <cuda_fp16.h>
#include <math.h>
#include <stdint.h>

#define N_NODES 100000
#define N_EDGES 1600000
#define NBLK    ((N_NODES + 127) / 128)      // 782
#define SCAN_CHUNK 4096
#define SCAN_NB ((N_NODES + SCAN_CHUNK - 1) / SCAN_CHUNK)   // 25
#define PAD 136   // bf16 elems per SMEM row: 272B stride -> conflict-free ldmatrix

// ---------------- scratch (static device globals; no allocation) ----------------
__device__ __half g_Uh[(size_t)N_NODES * 128]; // u = inv_sqrt * (h @ W), fp16
__device__ float g_H[(size_t)N_NODES * 128];   // layer activations (fp32)
__device__ __nv_bfloat16 g_Wbf[114688];        // W images [n][k], hi+lo per layer
__device__ int   g_srcSorted[N_EDGES];
__device__ int   g_cnt[N_NODES];
__device__ int   g_rowstart[N_NODES + 1];
__device__ int   g_cursor[N_NODES];
__device__ float g_invs[N_NODES];
__device__ int   g_is64;
__device__ int   g_bsum[SCAN_NB];
__device__ int   g_boff[SCAN_NB];
__device__ int   g_total;

// W image element offsets (in g_Wbf)
#define W1_HI 0
#define W1_LO 16384
#define W2_HI 32768
#define W2_LO 49152
#define W3_HI 65536
#define W3_LO 81920
#define WO_HI 98304
#define WO_LO 106496

// ---------------- mma helpers ----------------
__device__ __forceinline__ void ldsm4(uint32_t* r, const __nv_bfloat16* p) {
    uint32_t a = (uint32_t)__cvta_generic_to_shared(p);
    asm volatile("ldmatrix.sync.aligned.m8n8.x4.shared.b16 {%0,%1,%2,%3}, [%4];"
                 : "=r"(r[0]), "=r"(r[1]), "=r"(r[2]), "=r"(r[3]) : "r"(a));
}

__device__ __forceinline__ void mma16816(float* c, const uint32_t* a, const uint32_t* b) {
    asm volatile(
        "mma.sync.aligned.m16n8k16.row.col.f32.bf16.bf16.f32 "
        "{%0,%1,%2,%3}, {%4,%5,%6,%7}, {%8,%9}, {%0,%1,%2,%3};"
        : "+f"(c[0]), "+f"(c[1]), "+f"(c[2]), "+f"(c[3])
        : "r"(a[0]), "r"(a[1]), "r"(a[2]), "r"(a[3]), "r"(b[0]), "r"(b[1]));
}

// ---------------- dtype probe ----------------
__global__ void detect_kernel(const int* __restrict__ ei_raw) {
    if (blockIdx.x == 0 && threadIdx.x == 0) {
        int ok64 = 1;
        #pragma unroll 4
        for (int i = 0; i < 2048; i += 2)
            if (ei_raw[i + 1] != 0) { ok64 = 0; break; }
        g_is64 = ok64;
    }
}

__device__ __forceinline__ int load_idx(const void* ei, long long pos) {
    if (g_is64) return (int)((const long long*)ei)[pos];
    return ((const int*)ei)[pos];
}

// ---------------- graph preprocessing ----------------
__global__ void reset_kernel() {
    int i = blockIdx.x * blockDim.x + threadIdx.x;
    if (i < N_NODES) g_cnt[i] = 0;
}

__global__ void count_kernel(const void* __restrict__ ei) {
    int e = blockIdx.x * blockDim.x + threadIdx.x;
    if (e < N_EDGES) {
        int d = load_idx(ei, (long long)N_EDGES + e);
        if (d >= 0 && d < N_NODES) atomicAdd(&g_cnt[d], 1);
    }
}

__global__ __launch_bounds__(1024) void scan_local_kernel() {
    __shared__ int wsum[32];
    int tid = threadIdx.x, lane = tid & 31, wid = tid >> 5;
    int i0 = blockIdx.x * SCAN_CHUNK + tid * 4;

    int v0 = (i0 + 0 < N_NODES) ? g_cnt[i0 + 0] : 0;
    int v1 = (i0 + 1 < N_NODES) ? g_cnt[i0 + 1] : 0;
    int v2 = (i0 + 2 < N_NODES) ? g_cnt[i0 + 2] : 0;
    int v3 = (i0 + 3 < N_NODES) ? g_cnt[i0 + 3] : 0;
    int t = v0 + v1 + v2 + v3;

    int x = t;
    #pragma unroll
    for (int off = 1; off < 32; off <<= 1) {
        int y = __shfl_up_sync(0xffffffffu, x, off);
        if (lane >= off) x += y;
    }
    if (lane == 31) wsum[wid] = x;
    __syncthreads();
    if (wid == 0) {
        int w = wsum[lane];
        #pragma unroll
        for (int off = 1; off < 32; off <<= 1) {
            int y = __shfl_up_sync(0xffffffffu, w, off);
            if (lane >= off) w += y;
        }
        wsum[lane] = w;
    }
    __syncthreads();

    int run = (wid ? wsum[wid - 1] : 0) + (x - t);
    if (i0 + 0 < N_NODES) { g_rowstart[i0+0] = run; run += v0; }
    if (i0 + 1 < N_NODES) { g_rowstart[i0+1] = run; run += v1; }
    if (i0 + 2 < N_NODES) { g_rowstart[i0+2] = run; run += v2; }
    if (i0 + 3 < N_NODES) { g_rowstart[i0+3] = run; run += v3; }
    if (tid == 0) g_bsum[blockIdx.x] = wsum[31];
}

__global__ void scan_bsums_kernel() {
    int lane = threadIdx.x;
    int v = (lane < SCAN_NB) ? g_bsum[lane] : 0;
    int x = v;
    #pragma unroll
    for (int off = 1; off < 32; off <<= 1) {
        int y = __shfl_up_sync(0xffffffffu, x, off);
        if (lane >= off) x += y;
    }
    if (lane < SCAN_NB) g_boff[lane] = x - v;
    if (lane == 31) g_total = x;
}

__global__ void scan_finalize_kernel() {
    int i = blockIdx.x * blockDim.x + threadIdx.x;
    if (i < N_NODES) {
        int v = g_rowstart[i] + g_boff[i >> 12];
        g_rowstart[i] = v;
        g_cursor[i] = v;
        g_invs[i] = rsqrtf((float)(g_cnt[i] + 1));
    }
    if (i == 0) g_rowstart[N_NODES] = g_total;
}

__global__ void build_kernel(const void* __restrict__ ei) {
    int e = blockIdx.x * blockDim.x + threadIdx.x;
    if (e < N_EDGES) {
        int s = load_idx(ei, e);
        int d = load_idx(ei, (long long)N_EDGES + e);
        if (s >= 0 && s < N_NODES && d >= 0 && d < N_NODES) {
            int p = atomicAdd(&g_cursor[d], 1);
            if (p >= 0 && p < N_EDGES) g_srcSorted[p] = s;
        }
    }
}

// ---------------- weight image prep: [k][n] fp32 -> [n][k] bf16 hi/lo ----------------
__global__ void prep_w_kernel(const float* __restrict__ W, int N, int off_hi, int off_lo) {
    int e = blockIdx.x * blockDim.x + threadIdx.x;
    if (e >= 128 * N) return;
    int k = e / N, n = e % N;
    float v = W[e];
    __nv_bfloat16 hb = __float2bfloat16(v);
    __nv_bfloat16 lb = __float2bfloat16(v - __bfloat162float(hb));
    g_Wbf[off_hi + n * 128 + k] = hb;
    g_Wbf[off_lo + n * 128 + k] = lb;
}

// ---------------- tensor-core GEMM (mma.sync bf16, split 3-term) ----------------
// D[128, N] = X[128,128] @ W ; per-row scale (invs) / bias in epilogue.
// HALFOUT: write U as fp16 (aggregation operand). Else fp32 to Yout.
template <int N, bool XEXT, bool SCALE, bool BIAS, bool HALFOUT>
__global__ __launch_bounds__(256) void gemm_mma(
    const float* __restrict__ Xext, int w_hi, int w_lo,
    const float* __restrict__ bias, float* __restrict__ Yout)
{
    extern __shared__ __align__(16) __nv_bfloat16 sm[];
    __nv_bfloat16* Ah = sm;                         // [128][PAD]
    __nv_bfloat16* Al = Ah + 128 * PAD;
    __nv_bfloat16* Bh = Al + 128 * PAD;             // [N][PAD]
    __nv_bfloat16* Bl = Bh + N * PAD;

    const float* X = XEXT ? Xext : g_H;

    int tid = threadIdx.x;
    int lane = tid & 31, warp = tid >> 5;
    int r0 = blockIdx.x * 128;

    // ---- stage A: load fp32, split to bf16 hi/lo ----
    #pragma unroll
    for (int i = 0; i < 16; i++) {
        int j = tid + i * 256;            // 4096 float4 groups
        int row = j >> 5, c4 = (j & 31) << 2;
        float4 v = make_float4(0.f, 0.f, 0.f, 0.f);
        if (r0 + row < N_NODES)
            v = *(const float4*)&X[(size_t)(r0 + row) * 128 + c4];
        float vv[4] = {v.x, v.y, v.z, v.w};
        uint32_t h[4], l[4];
        #pragma unroll
        for (int q = 0; q < 4; q++) {
            __nv_bfloat16 hb = __float2bfloat16(vv[q]);
            h[q] = (uint32_t)__bfloat16_as_ushort(hb);
            l[q] = (uint32_t)__bfloat16_as_ushort(
                       __float2bfloat16(vv[q] - __bfloat162float(hb)));
        }
        *(uint2*)&Ah[row * PAD + c4] = make_uint2(h[0] | (h[1] << 16), h[2] | (h[3] << 16));
        *(uint2*)&Al[row * PAD + c4] = make_uint2(l[0] | (l[1] << 16), l[2] | (l[3] << 16));
    }
    // ---- stage B: copy prepped bf16 images ----
    #pragma unroll
    for (int i = 0; i < N * 16 / 256; i++) {
        int j = tid + i * 256;
        int row = j >> 4, q = j & 15;
        *(uint4*)&Bh[row * PAD + q * 8] = *(const uint4*)&g_Wbf[w_hi + row * 128 + q * 8];
        *(uint4*)&Bl[row * PAD + q * 8] = *(const uint4*)&g_Wbf[w_lo + row * 128 + q * 8];
    }
    __syncthreads();

    // warp layout: 4 (M) x 2 (N); warp tile 32 x (N/2)
    constexpr int NT = N / 16;            // n-tiles (8 wide) per warp: 8 or 4
    int wm = (warp & 3) * 32;
    int wn = (warp >> 2) * (N / 2);

    float acc[2][NT][4];
    #pragma unroll
    for (int mt = 0; mt < 2; mt++)
        #pragma unroll
        for (int nt = 0; nt < NT; nt++)
            #pragma unroll
            for (int q = 0; q < 4; q++) acc[mt][nt][q] = 0.f;

    int arow = lane & 15, acol = (lane >> 4) << 3;
    int brow = (lane & 7) + ((lane >> 4) << 3), bcol = ((lane >> 3) & 1) << 3;

    #pragma unroll
    for (int kk = 0; kk < 128; kk += 16) {
        uint32_t ah[2][4], al[2][4];
        ldsm4(ah[0], Ah + (wm + arow) * PAD + kk + acol);
        ldsm4(ah[1], Ah + (wm + 16 + arow) * PAD + kk + acol);
        ldsm4(al[0], Al + (wm + arow) * PAD + kk + acol);
        ldsm4(al[1], Al + (wm + 16 + arow) * PAD + kk + acol);

        uint32_t bh[NT][2], bl[NT][2];
        #pragma unroll
        for (int p = 0; p < NT / 2; p++) {
            uint32_t t[4];
            const __nv_bfloat16* pb = Bh + (wn + p * 16 + brow) * PAD + kk + bcol;
            ldsm4(t, pb);
            bh[2*p][0] = t[0]; bh[2*p][1] = t[1];
            bh[2*p+1][0] = t[2]; bh[2*p+1][1] = t[3];
            const __nv_bfloat16* pl = Bl + (wn + p * 16 + brow) * PAD + kk + bcol;
            ldsm4(t, pl);
            bl[2*p][0] = t[0]; bl[2*p][1] = t[1];
            bl[2*p+1][0] = t[2]; bl[2*p+1][1] = t[3];
        }

        #pragma unroll
        for (int mt = 0; mt < 2; mt++)
            #pragma unroll
            for (int nt = 0; nt < NT; nt++) {
                mma16816(acc[mt][nt], ah[mt], bh[nt]);
                mma16816(acc[mt][nt], ah[mt], bl[nt]);
                mma16816(acc[mt][nt], al[mt], bh[nt]);
            }
    }

    // ---- epilogue ----
    #pragma unroll
    for (int mt = 0; mt < 2; mt++) {
        int r1 = r0 + wm + mt * 16 + (lane >> 2);
        int r2 = r1 + 8;
        float s1 = 1.f, s2 = 1.f;
        if (SCALE) {
            if (r1 < N_NODES) s1 = g_invs[r1];
            if (r2 < N_NODES) s2 = g_invs[r2];
        }
        #pragma unroll
        for (int nt = 0; nt < NT; nt++) {
            int col = wn + nt * 8 + ((lane & 3) << 1);
            float bx = 0.f, by = 0.f;
            if (BIAS) { bx = bias[col]; by = bias[col + 1]; }
            if (r1 < N_NODES) {
                float ox = acc[mt][nt][0] * s1 + bx;
                float oy = acc[mt][nt][1] * s1 + by;
                if (HALFOUT)
                    *(__half2*)&g_Uh[(size_t)r1 * N + col] = __floats2half2_rn(ox, oy);
                else
                    *(float2*)&Yout[(size_t)r1 * N + col] = make_float2(ox, oy);
            }
            if (r2 < N_NODES) {
                float ox = acc[mt][nt][2] * s2 + bx;
                float oy = acc[mt][nt][3] * s2 + by;
                if (HALFOUT)
                    *(__half2*)&g_Uh[(size_t)r2 * N + col] = __floats2half2_rn(ox, oy);
                else
                    *(float2*)&Yout[(size_t)r2 * N + col] = make_float2(ox, oy);
            }
        }
    }
}

// ---------------- aggregation: warp per node, pull fp16 rows over CSR ----------------
// H[d] = act( inv_sqrt[d] * (U[d] + sum_{src} U[src]) + b ), accumulate fp32
template <bool RELU>
__global__ __launch_bounds__(256) void agg_kernel(const float* __restrict__ bias) {
    int gw = (blockIdx.x * 256 + threadIdx.x) >> 5;
    int lane = threadIdx.x & 31;
    if (gw >= N_NODES) return;

    const uint2* Up = (const uint2*)g_Uh;   // 4 halves per lane

    float4 a;
    {
        uint2 w = Up[(size_t)gw * 32 + lane];          // self-loop term
        float2 f0 = __half22float2(*(__half2*)&w.x);
        float2 f1 = __half22float2(*(__half2*)&w.y);
        a = make_float4(f0.x, f0.y, f1.x, f1.y);
    }
    int beg = g_rowstart[gw];
    int end = g_rowstart[gw + 1];

    int j = beg;
    for (; j + 4 <= end; j += 4) {
        int s0 = g_srcSorted[j + 0];
        int s1 = g_srcSorted[j + 1];
        int s2 = g_srcSorted[j + 2];
        int s3 = g_srcSorted[j + 3];
        uint2 w0 = Up[(size_t)s0 * 32 + lane];
        uint2 w1 = Up[(size_t)s1 * 32 + lane];
        uint2 w2 = Up[(size_t)s2 * 32 + lane];
        uint2 w3 = Up[(size_t)s3 * 32 + lane];
        float2 p;
        p = __half22float2(*(__half2*)&w0.x); a.x += p.x; a.y += p.y;
        p = __half22float2(*(__half2*)&w0.y); a.z += p.x; a.w += p.y;
        p = __half22float2(*(__half2*)&w1.x); a.x += p.x; a.y += p.y;
        p = __half22float2(*(__half2*)&w1.y); a.z += p.x; a.w += p.y;
        p = __half22float2(*(__half2*)&w2.x); a.x += p.x; a.y += p.y;
        p = __half22float2(*(__half2*)&w2.y); a.z += p.x; a.w += p.y;
        p = __half22float2(*(__half2*)&w3.x); a.x += p.x; a.y += p.y;
        p = __half22float2(*(__half2*)&w3.y); a.z += p.x; a.w += p.y;
    }
    for (; j < end; j++) {
        int s = g_srcSorted[j];
        uint2 w = Up[(size_t)s * 32 + lane];
        float2 p;
        p = __half22float2(*(__half2*)&w.x); a.x += p.x; a.y += p.y;
        p = __half22float2(*(__half2*)&w.y); a.z += p.x; a.w += p.y;
    }

    float is = g_invs[gw];
    float4 b4 = ((const float4*)bias)[lane];
    float4 o;
    o.x = is * a.x + b4.x;
    o.y = is * a.y + b4.y;
    o.z = is * a.z + b4.z;
    o.w = is * a.w + b4.w;
    if (RELU) {
        o.x = fmaxf(o.x, 0.f);
        o.y = fmaxf(o.y, 0.f);
        o.z = fmaxf(o.z, 0.f);
        o.w = fmaxf(o.w, 0.f);
    }
    ((float4*)g_H)[(size_t)gw * 32 + lane] = o;
}

// ---------------- launch ----------------
extern "C" void kernel_launch(void* const* d_in, const int* in_sizes, int n_in,
                              void* d_out, int out_size)
{
    const float* x  = (const float*)d_in[0];
    const void*  ei = d_in[1];
    const float* W1 = (const float*)d_in[2];
    const float* b1 = (const float*)d_in[3];
    const float* W2 = (const float*)d_in[4];
    const float* b2 = (const float*)d_in[5];
    const float* W3 = (const float*)d_in[6];
    const float* b3 = (const float*)d_in[7];
    const float* Wo = (const float*)d_in[8];
    const float* bo = (const float*)d_in[9];
    float* out = (float*)d_out;

    const int SMEM128 = (2 * 128 * PAD + 2 * 128 * PAD) * 2;  // 139264 B
    const int SMEM64  = (2 * 128 * PAD + 2 * 64  * PAD) * 2;  // 104448 B
    cudaFuncSetAttribute(gemm_mma<128, true,  true,  false, true>,
                         cudaFuncAttributeMaxDynamicSharedMemorySize, SMEM128);
    cudaFuncSetAttribute(gemm_mma<128, false, true,  false, true>,
                         cudaFuncAttributeMaxDynamicSharedMemorySize, SMEM128);
    cudaFuncSetAttribute(gemm_mma<64,  false, false, true,  false>,
                         cudaFuncAttributeMaxDynamicSharedMemorySize, SMEM64);

    // graph preprocessing (rebuilt every call; graph-replay deterministic)
    detect_kernel<<<1, 32>>>((const int*)ei);
    reset_kernel<<<(N_NODES + 255) / 256, 256>>>();
    count_kernel<<<(N_EDGES + 255) / 256, 256>>>(ei);
    scan_local_kernel<<<SCAN_NB, 1024>>>();
    scan_bsums_kernel<<<1, 32>>>();
    scan_finalize_kernel<<<(N_NODES + 255) / 256, 256>>>();
    build_kernel<<<(N_EDGES + 255) / 256, 256>>>(ei);

    // weight images
    prep_w_kernel<<<64, 256>>>(W1, 128, W1_HI, W1_LO);
    prep_w_kernel<<<64, 256>>>(W2, 128, W2_HI, W2_LO);
    prep_w_kernel<<<64, 256>>>(W3, 128, W3_HI, W3_LO);
    prep_w_kernel<<<32, 256>>>(Wo, 64,  WO_HI, WO_LO);

    const int AB = (N_NODES + 7) / 8;

    // layer 1
    gemm_mma<128, true,  true,  false, true><<<NBLK, 256, SMEM128>>>(x, W1_HI, W1_LO, nullptr, nullptr);
    agg_kernel<true><<<AB, 256>>>(b1);
    // layer 2
    gemm_mma<128, false, true,  false, true><<<NBLK, 256, SMEM128>>>(nullptr, W2_HI, W2_LO, nullptr, nullptr);
    agg_kernel<true><<<AB, 256>>>(b2);
    // layer 3 (no relu)
    gemm_mma<128, false, true,  false, true><<<NBLK, 256, SMEM128>>>(nullptr, W3_HI, W3_LO, nullptr, nullptr);
    agg_kernel<false><<<AB, 256>>>(b3);
    // output projection (fp32 out)
    gemm_mma<64, false, false, true, false><<<NBLK, 256, SMEM64>>>(nullptr, WO_HI, WO_LO, bo, out);
}

// round 11
// speedup vs baseline: 2.1742x; 1.2753x over previous
#include <cuda_runtime.h>
#include <cuda_bf16.h>
#include <cuda_fp16.h>
#include <math.h>
#include <stdint.h>

#define N_NODES 100000
#define N_EDGES 1600000
#define NBLK    ((N_NODES + 127) / 128)      // 782
#define SCAN_CHUNK 4096
#define SCAN_NB ((N_NODES + SCAN_CHUNK - 1) / SCAN_CHUNK)   // 25
#define PAD 136   // 16-bit elems per SMEM row: 272B stride -> conflict-free ldmatrix

// ---------------- scratch (static device globals; no allocation) ----------------
__device__ __half g_Uh[(size_t)N_NODES * 128]; // u = inv_sqrt * (h @ W), fp16
__device__ float g_H[(size_t)N_NODES * 128];   // layer activations (fp32)
__device__ __half g_Whf[3 * 16384];            // W1..W3 fp16 images [n][k]
__device__ __nv_bfloat16 g_Wbf[16384];         // Wout bf16 hi/lo images [n][k]
__device__ int   g_srcSorted[N_EDGES];
__device__ int   g_cnt[N_NODES];
__device__ int   g_rowstart[N_NODES + 1];
__device__ int   g_cursor[N_NODES];
__device__ float g_invs[N_NODES];
__device__ int   g_is64;
__device__ int   g_bsum[SCAN_NB];
__device__ int   g_boff[SCAN_NB];
__device__ int   g_total;

#define WO_HI 0
#define WO_LO 8192

// ---------------- mma helpers ----------------
__device__ __forceinline__ void ldsm4(uint32_t* r, const void* p) {
    uint32_t a = (uint32_t)__cvta_generic_to_shared(p);
    asm volatile("ldmatrix.sync.aligned.m8n8.x4.shared.b16 {%0,%1,%2,%3}, [%4];"
                 : "=r"(r[0]), "=r"(r[1]), "=r"(r[2]), "=r"(r[3]) : "r"(a));
}

__device__ __forceinline__ void mma_bf16(float* c, const uint32_t* a, const uint32_t* b) {
    asm volatile(
        "mma.sync.aligned.m16n8k16.row.col.f32.bf16.bf16.f32 "
        "{%0,%1,%2,%3}, {%4,%5,%6,%7}, {%8,%9}, {%0,%1,%2,%3};"
        : "+f"(c[0]), "+f"(c[1]), "+f"(c[2]), "+f"(c[3])
        : "r"(a[0]), "r"(a[1]), "r"(a[2]), "r"(a[3]), "r"(b[0]), "r"(b[1]));
}

__device__ __forceinline__ void mma_fp16(float* c, const uint32_t* a, const uint32_t* b) {
    asm volatile(
        "mma.sync.aligned.m16n8k16.row.col.f32.f16.f16.f32 "
        "{%0,%1,%2,%3}, {%4,%5,%6,%7}, {%8,%9}, {%0,%1,%2,%3};"
        : "+f"(c[0]), "+f"(c[1]), "+f"(c[2]), "+f"(c[3])
        : "r"(a[0]), "r"(a[1]), "r"(a[2]), "r"(a[3]), "r"(b[0]), "r"(b[1]));
}

// ---------------- dtype probe (parallel) ----------------
__global__ void detect_kernel(const int* __restrict__ ei_raw) {
    int lane = threadIdx.x;
    int bad = 0;
    #pragma unroll 4
    for (int i = lane; i < 1024; i += 32)
        bad |= (ei_raw[2 * i + 1] != 0);
    unsigned m = __ballot_sync(0xffffffffu, bad);
    if (lane == 0) g_is64 = (m == 0);
}

__device__ __forceinline__ int load_idx(const void* ei, long long pos) {
    if (g_is64) return (int)((const long long*)ei)[pos];
    return ((const int*)ei)[pos];
}

// ---------------- graph preprocessing ----------------
__global__ void reset_kernel() {
    int i = blockIdx.x * blockDim.x + threadIdx.x;
    if (i < N_NODES) g_cnt[i] = 0;
}

__global__ void count_kernel(const void* __restrict__ ei) {
    int e = blockIdx.x * blockDim.x + threadIdx.x;
    if (e < N_EDGES) {
        int d = load_idx(ei, (long long)N_EDGES + e);
        if (d >= 0 && d < N_NODES) atomicAdd(&g_cnt[d], 1);
    }
}

__global__ __launch_bounds__(1024) void scan_local_kernel() {
    __shared__ int wsum[32];
    int tid = threadIdx.x, lane = tid & 31, wid = tid >> 5;
    int i0 = blockIdx.x * SCAN_CHUNK + tid * 4;

    int v0 = (i0 + 0 < N_NODES) ? g_cnt[i0 + 0] : 0;
    int v1 = (i0 + 1 < N_NODES) ? g_cnt[i0 + 1] : 0;
    int v2 = (i0 + 2 < N_NODES) ? g_cnt[i0 + 2] : 0;
    int v3 = (i0 + 3 < N_NODES) ? g_cnt[i0 + 3] : 0;
    int t = v0 + v1 + v2 + v3;

    int x = t;
    #pragma unroll
    for (int off = 1; off < 32; off <<= 1) {
        int y = __shfl_up_sync(0xffffffffu, x, off);
        if (lane >= off) x += y;
    }
    if (lane == 31) wsum[wid] = x;
    __syncthreads();
    if (wid == 0) {
        int w = wsum[lane];
        #pragma unroll
        for (int off = 1; off < 32; off <<= 1) {
            int y = __shfl_up_sync(0xffffffffu, w, off);
            if (lane >= off) w += y;
        }
        wsum[lane] = w;
    }
    __syncthreads();

    int run = (wid ? wsum[wid - 1] : 0) + (x - t);
    if (i0 + 0 < N_NODES) { g_rowstart[i0+0] = run; run += v0; }
    if (i0 + 1 < N_NODES) { g_rowstart[i0+1] = run; run += v1; }
    if (i0 + 2 < N_NODES) { g_rowstart[i0+2] = run; run += v2; }
    if (i0 + 3 < N_NODES) { g_rowstart[i0+3] = run; run += v3; }
    if (tid == 0) g_bsum[blockIdx.x] = wsum[31];
}

__global__ void scan_bsums_kernel() {
    int lane = threadIdx.x;
    int v = (lane < SCAN_NB) ? g_bsum[lane] : 0;
    int x = v;
    #pragma unroll
    for (int off = 1; off < 32; off <<= 1) {
        int y = __shfl_up_sync(0xffffffffu, x, off);
        if (lane >= off) x += y;
    }
    if (lane < SCAN_NB) g_boff[lane] = x - v;
    if (lane == 31) g_total = x;
}

__global__ void scan_finalize_kernel() {
    int i = blockIdx.x * blockDim.x + threadIdx.x;
    if (i < N_NODES) {
        int v = g_rowstart[i] + g_boff[i >> 12];
        g_rowstart[i] = v;
        g_cursor[i] = v;
        g_invs[i] = rsqrtf((float)(g_cnt[i] + 1));
    }
    if (i == 0) g_rowstart[N_NODES] = g_total;
}

__global__ void build_kernel(const void* __restrict__ ei) {
    int e = blockIdx.x * blockDim.x + threadIdx.x;
    if (e < N_EDGES) {
        int s = load_idx(ei, e);
        int d = load_idx(ei, (long long)N_EDGES + e);
        if (s >= 0 && s < N_NODES && d >= 0 && d < N_NODES) {
            int p = atomicAdd(&g_cursor[d], 1);
            if (p >= 0 && p < N_EDGES) g_srcSorted[p] = s;
        }
    }
}

// ---------------- weight image prep ----------------
// fp16 image: [k][n] fp32 -> [n][k] fp16 (hidden layers)
__global__ void prep_wf_kernel(const float* __restrict__ W, int off) {
    int e = blockIdx.x * blockDim.x + threadIdx.x;
    if (e >= 128 * 128) return;
    int k = e >> 7, n = e & 127;
    g_Whf[off + n * 128 + k] = __float2half_rn(W[e]);
}

// bf16 hi/lo image (output layer, N=64)
__global__ void prep_w_kernel(const float* __restrict__ W, int N, int off_hi, int off_lo) {
    int e = blockIdx.x * blockDim.x + threadIdx.x;
    if (e >= 128 * N) return;
    int k = e / N, n = e % N;
    float v = W[e];
    __nv_bfloat16 hb = __float2bfloat16(v);
    __nv_bfloat16 lb = __float2bfloat16(v - __bfloat162float(hb));
    g_Wbf[off_hi + n * 128 + k] = hb;
    g_Wbf[off_lo + n * 128 + k] = lb;
}

// ---------------- hidden-layer GEMM: single-pass fp16 mma ----------------
// g_Uh[128-row tile] = invs * (X @ W)   (fp16 out)
template <bool XEXT>
__global__ __launch_bounds__(256) void gemm_fp16(const float* __restrict__ Xext, int w_off) {
    extern __shared__ __align__(16) __half smh[];
    __half* Af = smh;                 // [128][PAD]
    __half* Bf = Af + 128 * PAD;      // [128][PAD]

    const float* X = XEXT ? Xext : g_H;

    int tid = threadIdx.x;
    int lane = tid & 31, warp = tid >> 5;
    int r0 = blockIdx.x * 128;

    // stage A: fp32 -> fp16
    #pragma unroll
    for (int i = 0; i < 16; i++) {
        int j = tid + i * 256;
        int row = j >> 5, c4 = (j & 31) << 2;
        float4 v = make_float4(0.f, 0.f, 0.f, 0.f);
        if (r0 + row < N_NODES)
            v = *(const float4*)&X[(size_t)(r0 + row) * 128 + c4];
        __half2 h0 = __floats2half2_rn(v.x, v.y);
        __half2 h1 = __floats2half2_rn(v.z, v.w);
        *(uint2*)&Af[row * PAD + c4] =
            make_uint2(*(uint32_t*)&h0, *(uint32_t*)&h1);
    }
    // stage B: copy fp16 image
    #pragma unroll
    for (int i = 0; i < 8; i++) {
        int j = tid + i * 256;
        int row = j >> 4, q = j & 15;
        *(uint4*)&Bf[row * PAD + q * 8] = *(const uint4*)&g_Whf[w_off + row * 128 + q * 8];
    }
    __syncthreads();

    // warp layout: 4 (M) x 2 (N); warp tile 32 x 64
    int wm = (warp & 3) * 32;
    int wn = (warp >> 2) * 64;

    float acc[2][8][4];
    #pragma unroll
    for (int mt = 0; mt < 2; mt++)
        #pragma unroll
        for (int nt = 0; nt < 8; nt++)
            #pragma unroll
            for (int q = 0; q < 4; q++) acc[mt][nt][q] = 0.f;

    int arow = lane & 15, acol = (lane >> 4) << 3;
    int brow = (lane & 7) + ((lane >> 4) << 3), bcol = ((lane >> 3) & 1) << 3;

    #pragma unroll
    for (int kk = 0; kk < 128; kk += 16) {
        uint32_t af[2][4];
        ldsm4(af[0], Af + (wm + arow) * PAD + kk + acol);
        ldsm4(af[1], Af + (wm + 16 + arow) * PAD + kk + acol);

        uint32_t bf[8][2];
        #pragma unroll
        for (int p = 0; p < 4; p++) {
            uint32_t t[4];
            ldsm4(t, Bf + (wn + p * 16 + brow) * PAD + kk + bcol);
            bf[2*p][0] = t[0]; bf[2*p][1] = t[1];
            bf[2*p+1][0] = t[2]; bf[2*p+1][1] = t[3];
        }

        #pragma unroll
        for (int mt = 0; mt < 2; mt++)
            #pragma unroll
            for (int nt = 0; nt < 8; nt++)
                mma_fp16(acc[mt][nt], af[mt], bf[nt]);
    }

    // epilogue: scale by invs, write fp16
    #pragma unroll
    for (int mt = 0; mt < 2; mt++) {
        int r1 = r0 + wm + mt * 16 + (lane >> 2);
        int r2 = r1 + 8;
        float s1 = (r1 < N_NODES) ? g_invs[r1] : 0.f;
        float s2 = (r2 < N_NODES) ? g_invs[r2] : 0.f;
        #pragma unroll
        for (int nt = 0; nt < 8; nt++) {
            int col = wn + nt * 8 + ((lane & 3) << 1);
            if (r1 < N_NODES)
                *(__half2*)&g_Uh[(size_t)r1 * 128 + col] =
                    __floats2half2_rn(acc[mt][nt][0] * s1, acc[mt][nt][1] * s1);
            if (r2 < N_NODES)
                *(__half2*)&g_Uh[(size_t)r2 * 128 + col] =
                    __floats2half2_rn(acc[mt][nt][2] * s2, acc[mt][nt][3] * s2);
        }
    }
}

// ---------------- output GEMM: bf16 split 3-pass (N=64), fp32 out + bias ----------------
__global__ __launch_bounds__(256) void gemm_out(const float* __restrict__ bias,
                                                float* __restrict__ Yout) {
    constexpr int N = 64;
    extern __shared__ __align__(16) __nv_bfloat16 sm[];
    __nv_bfloat16* Ah = sm;                         // [128][PAD]
    __nv_bfloat16* Al = Ah + 128 * PAD;
    __nv_bfloat16* Bh = Al + 128 * PAD;             // [N][PAD]
    __nv_bfloat16* Bl = Bh + N * PAD;

    const float* X = g_H;

    int tid = threadIdx.x;
    int lane = tid & 31, warp = tid >> 5;
    int r0 = blockIdx.x * 128;

    #pragma unroll
    for (int i = 0; i < 16; i++) {
        int j = tid + i * 256;
        int row = j >> 5, c4 = (j & 31) << 2;
        float4 v = make_float4(0.f, 0.f, 0.f, 0.f);
        if (r0 + row < N_NODES)
            v = *(const float4*)&X[(size_t)(r0 + row) * 128 + c4];
        float vv[4] = {v.x, v.y, v.z, v.w};
        uint32_t h[4], l[4];
        #pragma unroll
        for (int q = 0; q < 4; q++) {
            __nv_bfloat16 hb = __float2bfloat16(vv[q]);
            h[q] = (uint32_t)__bfloat16_as_ushort(hb);
            l[q] = (uint32_t)__bfloat16_as_ushort(
                       __float2bfloat16(vv[q] - __bfloat162float(hb)));
        }
        *(uint2*)&Ah[row * PAD + c4] = make_uint2(h[0] | (h[1] << 16), h[2] | (h[3] << 16));
        *(uint2*)&Al[row * PAD + c4] = make_uint2(l[0] | (l[1] << 16), l[2] | (l[3] << 16));
    }
    #pragma unroll
    for (int i = 0; i < N * 16 / 256; i++) {
        int j = tid + i * 256;
        int row = j >> 4, q = j & 15;
        *(uint4*)&Bh[row * PAD + q * 8] = *(const uint4*)&g_Wbf[WO_HI + row * 128 + q * 8];
        *(uint4*)&Bl[row * PAD + q * 8] = *(const uint4*)&g_Wbf[WO_LO + row * 128 + q * 8];
    }
    __syncthreads();

    constexpr int NT = N / 16;   // 4
    int wm = (warp & 3) * 32;
    int wn = (warp >> 2) * (N / 2);

    float acc[2][NT][4];
    #pragma unroll
    for (int mt = 0; mt < 2; mt++)
        #pragma unroll
        for (int nt = 0; nt < NT; nt++)
            #pragma unroll
            for (int q = 0; q < 4; q++) acc[mt][nt][q] = 0.f;

    int arow = lane & 15, acol = (lane >> 4) << 3;
    int brow = (lane & 7) + ((lane >> 4) << 3), bcol = ((lane >> 3) & 1) << 3;

    #pragma unroll
    for (int kk = 0; kk < 128; kk += 16) {
        uint32_t ah[2][4], al[2][4];
        ldsm4(ah[0], Ah + (wm + arow) * PAD + kk + acol);
        ldsm4(ah[1], Ah + (wm + 16 + arow) * PAD + kk + acol);
        ldsm4(al[0], Al + (wm + arow) * PAD + kk + acol);
        ldsm4(al[1], Al + (wm + 16 + arow) * PAD + kk + acol);

        uint32_t bh[NT][2], bl[NT][2];
        #pragma unroll
        for (int p = 0; p < NT / 2; p++) {
            uint32_t t[4];
            ldsm4(t, Bh + (wn + p * 16 + brow) * PAD + kk + bcol);
            bh[2*p][0] = t[0]; bh[2*p][1] = t[1];
            bh[2*p+1][0] = t[2]; bh[2*p+1][1] = t[3];
            ldsm4(t, Bl + (wn + p * 16 + brow) * PAD + kk + bcol);
            bl[2*p][0] = t[0]; bl[2*p][1] = t[1];
            bl[2*p+1][0] = t[2]; bl[2*p+1][1] = t[3];
        }

        #pragma unroll
        for (int mt = 0; mt < 2; mt++)
            #pragma unroll
            for (int nt = 0; nt < NT; nt++) {
                mma_bf16(acc[mt][nt], ah[mt], bh[nt]);
                mma_bf16(acc[mt][nt], ah[mt], bl[nt]);
                mma_bf16(acc[mt][nt], al[mt], bh[nt]);
            }
    }

    #pragma unroll
    for (int mt = 0; mt < 2; mt++) {
        int r1 = r0 + wm + mt * 16 + (lane >> 2);
        int r2 = r1 + 8;
        #pragma unroll
        for (int nt = 0; nt < NT; nt++) {
            int col = wn + nt * 8 + ((lane & 3) << 1);
            float bx = bias[col], by = bias[col + 1];
            if (r1 < N_NODES)
                *(float2*)&Yout[(size_t)r1 * N + col] =
                    make_float2(acc[mt][nt][0] + bx, acc[mt][nt][1] + by);
            if (r2 < N_NODES)
                *(float2*)&Yout[(size_t)r2 * N + col] =
                    make_float2(acc[mt][nt][2] + bx, acc[mt][nt][3] + by);
        }
    }
}

// ---------------- aggregation: warp per node, pull fp16 rows over CSR ----------------
template <bool RELU>
__global__ __launch_bounds__(256) void agg_kernel(const float* __restrict__ bias) {
    int gw = (blockIdx.x * 256 + threadIdx.x) >> 5;
    int lane = threadIdx.x & 31;
    if (gw >= N_NODES) return;

    const uint2* Up = (const uint2*)g_Uh;   // 4 halves per lane

    float4 a;
    {
        uint2 w = Up[(size_t)gw * 32 + lane];          // self-loop term
        float2 f0 = __half22float2(*(__half2*)&w.x);
        float2 f1 = __half22float2(*(__half2*)&w.y);
        a = make_float4(f0.x, f0.y, f1.x, f1.y);
    }
    int beg = g_rowstart[gw];
    int end = g_rowstart[gw + 1];

    int j = beg;
    for (; j + 4 <= end; j += 4) {
        int s0 = g_srcSorted[j + 0];
        int s1 = g_srcSorted[j + 1];
        int s2 = g_srcSorted[j + 2];
        int s3 = g_srcSorted[j + 3];
        uint2 w0 = Up[(size_t)s0 * 32 + lane];
        uint2 w1 = Up[(size_t)s1 * 32 + lane];
        uint2 w2 = Up[(size_t)s2 * 32 + lane];
        uint2 w3 = Up[(size_t)s3 * 32 + lane];
        float2 p;
        p = __half22float2(*(__half2*)&w0.x); a.x += p.x; a.y += p.y;
        p = __half22float2(*(__half2*)&w0.y); a.z += p.x; a.w += p.y;
        p = __half22float2(*(__half2*)&w1.x); a.x += p.x; a.y += p.y;
        p = __half22float2(*(__half2*)&w1.y); a.z += p.x; a.w += p.y;
        p = __half22float2(*(__half2*)&w2.x); a.x += p.x; a.y += p.y;
        p = __half22float2(*(__half2*)&w2.y); a.z += p.x; a.w += p.y;
        p = __half22float2(*(__half2*)&w3.x); a.x += p.x; a.y += p.y;
        p = __half22float2(*(__half2*)&w3.y); a.z += p.x; a.w += p.y;
    }
    for (; j < end; j++) {
        int s = g_srcSorted[j];
        uint2 w = Up[(size_t)s * 32 + lane];
        float2 p;
        p = __half22float2(*(__half2*)&w.x); a.x += p.x; a.y += p.y;
        p = __half22float2(*(__half2*)&w.y); a.z += p.x; a.w += p.y;
    }

    float is = g_invs[gw];
    float4 b4 = ((const float4*)bias)[lane];
    float4 o;
    o.x = is * a.x + b4.x;
    o.y = is * a.y + b4.y;
    o.z = is * a.z + b4.z;
    o.w = is * a.w + b4.w;
    if (RELU) {
        o.x = fmaxf(o.x, 0.f);
        o.y = fmaxf(o.y, 0.f);
        o.z = fmaxf(o.z, 0.f);
        o.w = fmaxf(o.w, 0.f);
    }
    ((float4*)g_H)[(size_t)gw * 32 + lane] = o;
}

// ---------------- launch ----------------
extern "C" void kernel_launch(void* const* d_in, const int* in_sizes, int n_in,
                              void* d_out, int out_size)
{
    const float* x  = (const float*)d_in[0];
    const void*  ei = d_in[1];
    const float* W1 = (const float*)d_in[2];
    const float* b1 = (const float*)d_in[3];
    const float* W2 = (const float*)d_in[4];
    const float* b2 = (const float*)d_in[5];
    const float* W3 = (const float*)d_in[6];
    const float* b3 = (const float*)d_in[7];
    const float* Wo = (const float*)d_in[8];
    const float* bo = (const float*)d_in[9];
    float* out = (float*)d_out;

    const int SMEM_F  = 2 * 128 * PAD * 2;                    // 69632 B (fp16 1-pass)
    const int SMEM64  = (2 * 128 * PAD + 2 * 64 * PAD) * 2;   // 104448 B (bf16 3-pass out)
    cudaFuncSetAttribute(gemm_fp16<true>,
                         cudaFuncAttributeMaxDynamicSharedMemorySize, SMEM_F);
    cudaFuncSetAttribute(gemm_fp16<false>,
                         cudaFuncAttributeMaxDynamicSharedMemorySize, SMEM_F);
    cudaFuncSetAttribute(gemm_out,
                         cudaFuncAttributeMaxDynamicSharedMemorySize, SMEM64);

    // graph preprocessing (rebuilt every call; graph-replay deterministic)
    detect_kernel<<<1, 32>>>((const int*)ei);
    reset_kernel<<<(N_NODES + 255) / 256, 256>>>();
    count_kernel<<<(N_EDGES + 255) / 256, 256>>>(ei);
    scan_local_kernel<<<SCAN_NB, 1024>>>();
    scan_bsums_kernel<<<1, 32>>>();
    scan_finalize_kernel<<<(N_NODES + 255) / 256, 256>>>();
    build_kernel<<<(N_EDGES + 255) / 256, 256>>>(ei);

    // weight images
    prep_wf_kernel<<<64, 256>>>(W1, 0);
    prep_wf_kernel<<<64, 256>>>(W2, 16384);
    prep_wf_kernel<<<64, 256>>>(W3, 32768);
    prep_w_kernel<<<32, 256>>>(Wo, 64, WO_HI, WO_LO);

    const int AB = (N_NODES + 7) / 8;

    // layer 1
    gemm_fp16<true><<<NBLK, 256, SMEM_F>>>(x, 0);
    agg_kernel<true><<<AB, 256>>>(b1);
    // layer 2
    gemm_fp16<false><<<NBLK, 256, SMEM_F>>>(nullptr, 16384);
    agg_kernel<true><<<AB, 256>>>(b2);
    // layer 3 (no relu)
    gemm_fp16<false><<<NBLK, 256, SMEM_F>>>(nullptr, 32768);
    agg_kernel<false><<<AB, 256>>>(b3);
    // output projection (bf16 3-pass, fp32 out)
    gemm_out<<<NBLK, 256, SMEM64>>>(bo, out);
}

// round 14
// speedup vs baseline: 2.1997x; 1.0118x over previous
#include <cuda_runtime.h>
#include <cuda_bf16.h>
#include <cuda_fp16.h>
#include <math.h>
#include <stdint.h>

#define N_NODES 100000
#define N_EDGES 1600000
#define NBLK    ((N_NODES + 127) / 128)      // 782
#define SCAN_CHUNK 4096
#define SCAN_NB ((N_NODES + SCAN_CHUNK - 1) / SCAN_CHUNK)   // 25
#define PAD 136   // 16-bit elems per SMEM row: 272B stride -> conflict-free ldmatrix

// ---------------- scratch (static device globals; no allocation) ----------------
__device__ __half g_Uh[(size_t)N_NODES * 128]; // u = inv_sqrt * (h @ W), fp16
__device__ __half g_Hh[(size_t)N_NODES * 128]; // layer activations, fp16
__device__ __half g_Whf[3 * 16384];            // W1..W3 fp16 images [n][k]
__device__ __nv_bfloat16 g_Wbf[16384];         // Wout bf16 hi/lo images [n][k]
__device__ int   g_srcSorted[N_EDGES];
__device__ int   g_cnt[N_NODES];
__device__ int   g_rowstart[N_NODES + 1];
__device__ int   g_cursor[N_NODES];
__device__ float g_invs[N_NODES];
__device__ int   g_is64;
__device__ int   g_bsum[SCAN_NB];
__device__ int   g_boff[SCAN_NB];
__device__ int   g_total;

#define WO_HI 0
#define WO_LO 8192

// ---------------- mma helpers ----------------
__device__ __forceinline__ void ldsm4(uint32_t* r, const void* p) {
    uint32_t a = (uint32_t)__cvta_generic_to_shared(p);
    asm volatile("ldmatrix.sync.aligned.m8n8.x4.shared.b16 {%0,%1,%2,%3}, [%4];"
                 : "=r"(r[0]), "=r"(r[1]), "=r"(r[2]), "=r"(r[3]) : "r"(a));
}

__device__ __forceinline__ void mma_bf16(float* c, const uint32_t* a, const uint32_t* b) {
    asm volatile(
        "mma.sync.aligned.m16n8k16.row.col.f32.bf16.bf16.f32 "
        "{%0,%1,%2,%3}, {%4,%5,%6,%7}, {%8,%9}, {%0,%1,%2,%3};"
        : "+f"(c[0]), "+f"(c[1]), "+f"(c[2]), "+f"(c[3])
        : "r"(a[0]), "r"(a[1]), "r"(a[2]), "r"(a[3]), "r"(b[0]), "r"(b[1]));
}

__device__ __forceinline__ void mma_fp16(float* c, const uint32_t* a, const uint32_t* b) {
    asm volatile(
        "mma.sync.aligned.m16n8k16.row.col.f32.f16.f16.f32 "
        "{%0,%1,%2,%3}, {%4,%5,%6,%7}, {%8,%9}, {%0,%1,%2,%3};"
        : "+f"(c[0]), "+f"(c[1]), "+f"(c[2]), "+f"(c[3])
        : "r"(a[0]), "r"(a[1]), "r"(a[2]), "r"(a[3]), "r"(b[0]), "r"(b[1]));
}

// ---------------- dtype probe (parallel) ----------------
__global__ void detect_kernel(const int* __restrict__ ei_raw) {
    int lane = threadIdx.x;
    int bad = 0;
    #pragma unroll 4
    for (int i = lane; i < 1024; i += 32)
        bad |= (ei_raw[2 * i + 1] != 0);
    unsigned m = __ballot_sync(0xffffffffu, bad);
    if (lane == 0) g_is64 = (m == 0);
}

__device__ __forceinline__ int load_idx(const void* ei, long long pos) {
    if (g_is64) return (int)((const long long*)ei)[pos];
    return ((const int*)ei)[pos];
}

// ---------------- graph preprocessing ----------------
__global__ void reset_kernel() {
    int i = blockIdx.x * blockDim.x + threadIdx.x;
    if (i < N_NODES) g_cnt[i] = 0;
}

__global__ void count_kernel(const void* __restrict__ ei) {
    int e = blockIdx.x * blockDim.x + threadIdx.x;
    if (e < N_EDGES) {
        int d = load_idx(ei, (long long)N_EDGES + e);
        if (d >= 0 && d < N_NODES) atomicAdd(&g_cnt[d], 1);
    }
}

__global__ __launch_bounds__(1024) void scan_local_kernel() {
    __shared__ int wsum[32];
    int tid = threadIdx.x, lane = tid & 31, wid = tid >> 5;
    int i0 = blockIdx.x * SCAN_CHUNK + tid * 4;

    int v0 = (i0 + 0 < N_NODES) ? g_cnt[i0 + 0] : 0;
    int v1 = (i0 + 1 < N_NODES) ? g_cnt[i0 + 1] : 0;
    int v2 = (i0 + 2 < N_NODES) ? g_cnt[i0 + 2] : 0;
    int v3 = (i0 + 3 < N_NODES) ? g_cnt[i0 + 3] : 0;
    int t = v0 + v1 + v2 + v3;

    int x = t;
    #pragma unroll
    for (int off = 1; off < 32; off <<= 1) {
        int y = __shfl_up_sync(0xffffffffu, x, off);
        if (lane >= off) x += y;
    }
    if (lane == 31) wsum[wid] = x;
    __syncthreads();
    if (wid == 0) {
        int w = wsum[lane];
        #pragma unroll
        for (int off = 1; off < 32; off <<= 1) {
            int y = __shfl_up_sync(0xffffffffu, w, off);
            if (lane >= off) w += y;
        }
        wsum[lane] = w;
    }
    __syncthreads();

    int run = (wid ? wsum[wid - 1] : 0) + (x - t);
    if (i0 + 0 < N_NODES) { g_rowstart[i0+0] = run; run += v0; }
    if (i0 + 1 < N_NODES) { g_rowstart[i0+1] = run; run += v1; }
    if (i0 + 2 < N_NODES) { g_rowstart[i0+2] = run; run += v2; }
    if (i0 + 3 < N_NODES) { g_rowstart[i0+3] = run; run += v3; }
    if (tid == 0) g_bsum[blockIdx.x] = wsum[31];
}

__global__ void scan_bsums_kernel() {
    int lane = threadIdx.x;
    int v = (lane < SCAN_NB) ? g_bsum[lane] : 0;
    int x = v;
    #pragma unroll
    for (int off = 1; off < 32; off <<= 1) {
        int y = __shfl_up_sync(0xffffffffu, x, off);
        if (lane >= off) x += y;
    }
    if (lane < SCAN_NB) g_boff[lane] = x - v;
    if (lane == 31) g_total = x;
}

__global__ void scan_finalize_kernel() {
    int i = blockIdx.x * blockDim.x + threadIdx.x;
    if (i < N_NODES) {
        int v = g_rowstart[i] + g_boff[i >> 12];
        g_rowstart[i] = v;
        g_cursor[i] = v;
        g_invs[i] = rsqrtf((float)(g_cnt[i] + 1));
    }
    if (i == 0) g_rowstart[N_NODES] = g_total;
}

__global__ void build_kernel(const void* __restrict__ ei) {
    int e = blockIdx.x * blockDim.x + threadIdx.x;
    if (e < N_EDGES) {
        int s = load_idx(ei, e);
        int d = load_idx(ei, (long long)N_EDGES + e);
        if (s >= 0 && s < N_NODES && d >= 0 && d < N_NODES) {
            int p = atomicAdd(&g_cursor[d], 1);
            if (p >= 0 && p < N_EDGES) g_srcSorted[p] = s;
        }
    }
}

// ---------------- weight image prep ----------------
__global__ void prep_wf_kernel(const float* __restrict__ W, int off) {
    int e = blockIdx.x * blockDim.x + threadIdx.x;
    if (e >= 128 * 128) return;
    int k = e >> 7, n = e & 127;
    g_Whf[off + n * 128 + k] = __float2half_rn(W[e]);
}

__global__ void prep_w_kernel(const float* __restrict__ W, int N, int off_hi, int off_lo) {
    int e = blockIdx.x * blockDim.x + threadIdx.x;
    if (e >= 128 * N) return;
    int k = e / N, n = e % N;
    float v = W[e];
    __nv_bfloat16 hb = __float2bfloat16(v);
    __nv_bfloat16 lb = __float2bfloat16(v - __bfloat162float(hb));
    g_Wbf[off_hi + n * 128 + k] = hb;
    g_Wbf[off_lo + n * 128 + k] = lb;
}

// ---------------- hidden-layer GEMM: single-pass fp16 mma ----------------
// g_Uh[128-row tile] = invs * (X @ W)   (fp16 out)
// XEXT: A from external fp32 x; else A = g_Hh (fp16, straight copy)
template <bool XEXT>
__global__ __launch_bounds__(256) void gemm_fp16(const float* __restrict__ Xext, int w_off) {
    extern __shared__ __align__(16) __half smh[];
    __half* Af = smh;                 // [128][PAD]
    __half* Bf = Af + 128 * PAD;      // [128][PAD]

    int tid = threadIdx.x;
    int lane = tid & 31, warp = tid >> 5;
    int r0 = blockIdx.x * 128;

    if (XEXT) {
        // stage A: fp32 -> fp16
        #pragma unroll
        for (int i = 0; i < 16; i++) {
            int j = tid + i * 256;
            int row = j >> 5, c4 = (j & 31) << 2;
            float4 v = make_float4(0.f, 0.f, 0.f, 0.f);
            if (r0 + row < N_NODES)
                v = *(const float4*)&Xext[(size_t)(r0 + row) * 128 + c4];
            __half2 h0 = __floats2half2_rn(v.x, v.y);
            __half2 h1 = __floats2half2_rn(v.z, v.w);
            *(uint2*)&Af[row * PAD + c4] =
                make_uint2(*(uint32_t*)&h0, *(uint32_t*)&h1);
        }
    } else {
        // stage A: fp16 straight copy. 128 rows x 16 uint4/row = 2048 uint4.
        #pragma unroll
        for (int i = 0; i < 8; i++) {
            int j = tid + i * 256;
            int row = j >> 4, q = j & 15;
            uint4 v = make_uint4(0u, 0u, 0u, 0u);
            if (r0 + row < N_NODES)
                v = *(const uint4*)&g_Hh[(size_t)(r0 + row) * 128 + q * 8];
            *(uint4*)&Af[row * PAD + q * 8] = v;
        }
    }
    // stage B: copy fp16 image
    #pragma unroll
    for (int i = 0; i < 8; i++) {
        int j = tid + i * 256;
        int row = j >> 4, q = j & 15;
        *(uint4*)&Bf[row * PAD + q * 8] = *(const uint4*)&g_Whf[w_off + row * 128 + q * 8];
    }
    __syncthreads();

    int wm = (warp & 3) * 32;
    int wn = (warp >> 2) * 64;

    float acc[2][8][4];
    #pragma unroll
    for (int mt = 0; mt < 2; mt++)
        #pragma unroll
        for (int nt = 0; nt < 8; nt++)
            #pragma unroll
            for (int q = 0; q < 4; q++) acc[mt][nt][q] = 0.f;

    int arow = lane & 15, acol = (lane >> 4) << 3;
    int brow = (lane & 7) + ((lane >> 4) << 3), bcol = ((lane >> 3) & 1) << 3;

    #pragma unroll
    for (int kk = 0; kk < 128; kk += 16) {
        uint32_t af[2][4];
        ldsm4(af[0], Af + (wm + arow) * PAD + kk + acol);
        ldsm4(af[1], Af + (wm + 16 + arow) * PAD + kk + acol);

        uint32_t bf[8][2];
        #pragma unroll
        for (int p = 0; p < 4; p++) {
            uint32_t t[4];
            ldsm4(t, Bf + (wn + p * 16 + brow) * PAD + kk + bcol);
            bf[2*p][0] = t[0]; bf[2*p][1] = t[1];
            bf[2*p+1][0] = t[2]; bf[2*p+1][1] = t[3];
        }

        #pragma unroll
        for (int mt = 0; mt < 2; mt++)
            #pragma unroll
            for (int nt = 0; nt < 8; nt++)
                mma_fp16(acc[mt][nt], af[mt], bf[nt]);
    }

    // epilogue: scale by invs, write fp16
    #pragma unroll
    for (int mt = 0; mt < 2; mt++) {
        int r1 = r0 + wm + mt * 16 + (lane >> 2);
        int r2 = r1 + 8;
        float s1 = (r1 < N_NODES) ? g_invs[r1] : 0.f;
        float s2 = (r2 < N_NODES) ? g_invs[r2] : 0.f;
        #pragma unroll
        for (int nt = 0; nt < 8; nt++) {
            int col = wn + nt * 8 + ((lane & 3) << 1);
            if (r1 < N_NODES)
                *(__half2*)&g_Uh[(size_t)r1 * 128 + col] =
                    __floats2half2_rn(acc[mt][nt][0] * s1, acc[mt][nt][1] * s1);
            if (r2 < N_NODES)
                *(__half2*)&g_Uh[(size_t)r2 * 128 + col] =
                    __floats2half2_rn(acc[mt][nt][2] * s2, acc[mt][nt][3] * s2);
        }
    }
}

// ---------------- output GEMM: bf16 split 3-pass (N=64), fp32 out + bias ----------------
// A = g_Hh (fp16); fp16 -> bf16 hi/lo split is EXACT.
__global__ __launch_bounds__(256) void gemm_out(const float* __restrict__ bias,
                                                float* __restrict__ Yout) {
    constexpr int N = 64;
    extern __shared__ __align__(16) __nv_bfloat16 sm[];
    __nv_bfloat16* Ah = sm;                         // [128][PAD]
    __nv_bfloat16* Al = Ah + 128 * PAD;
    __nv_bfloat16* Bh = Al + 128 * PAD;             // [N][PAD]
    __nv_bfloat16* Bl = Bh + N * PAD;

    int tid = threadIdx.x;
    int lane = tid & 31, warp = tid >> 5;
    int r0 = blockIdx.x * 128;

    #pragma unroll
    for (int i = 0; i < 16; i++) {
        int j = tid + i * 256;
        int row = j >> 5, c4 = (j & 31) << 2;
        uint2 hv = make_uint2(0u, 0u);
        if (r0 + row < N_NODES)
            hv = *(const uint2*)&g_Hh[(size_t)(r0 + row) * 128 + c4];
        const __half* hp = (const __half*)&hv;
        uint32_t h[4], l[4];
        #pragma unroll
        for (int q = 0; q < 4; q++) {
            float f = __half2float(hp[q]);
            __nv_bfloat16 hb = __float2bfloat16(f);
            h[q] = (uint32_t)__bfloat16_as_ushort(hb);
            l[q] = (uint32_t)__bfloat16_as_ushort(
                       __float2bfloat16(f - __bfloat162float(hb)));
        }
        *(uint2*)&Ah[row * PAD + c4] = make_uint2(h[0] | (h[1] << 16), h[2] | (h[3] << 16));
        *(uint2*)&Al[row * PAD + c4] = make_uint2(l[0] | (l[1] << 16), l[2] | (l[3] << 16));
    }
    #pragma unroll
    for (int i = 0; i < N * 16 / 256; i++) {
        int j = tid + i * 256;
        int row = j >> 4, q = j & 15;
        *(uint4*)&Bh[row * PAD + q * 8] = *(const uint4*)&g_Wbf[WO_HI + row * 128 + q * 8];
        *(uint4*)&Bl[row * PAD + q * 8] = *(const uint4*)&g_Wbf[WO_LO + row * 128 + q * 8];
    }
    __syncthreads();

    constexpr int NT = N / 16;   // 4
    int wm = (warp & 3) * 32;
    int wn = (warp >> 2) * (N / 2);

    float acc[2][NT][4];
    #pragma unroll
    for (int mt = 0; mt < 2; mt++)
        #pragma unroll
        for (int nt = 0; nt < NT; nt++)
            #pragma unroll
            for (int q = 0; q < 4; q++) acc[mt][nt][q] = 0.f;

    int arow = lane & 15, acol = (lane >> 4) << 3;
    int brow = (lane & 7) + ((lane >> 4) << 3), bcol = ((lane >> 3) & 1) << 3;

    #pragma unroll
    for (int kk = 0; kk < 128; kk += 16) {
        uint32_t ah[2][4], al[2][4];
        ldsm4(ah[0], Ah + (wm + arow) * PAD + kk + acol);
        ldsm4(ah[1], Ah + (wm + 16 + arow) * PAD + kk + acol);
        ldsm4(al[0], Al + (wm + arow) * PAD + kk + acol);
        ldsm4(al[1], Al + (wm + 16 + arow) * PAD + kk + acol);

        uint32_t bh[NT][2], bl[NT][2];
        #pragma unroll
        for (int p = 0; p < NT / 2; p++) {
            uint32_t t[4];
            ldsm4(t, Bh + (wn + p * 16 + brow) * PAD + kk + bcol);
            bh[2*p][0] = t[0]; bh[2*p][1] = t[1];
            bh[2*p+1][0] = t[2]; bh[2*p+1][1] = t[3];
            ldsm4(t, Bl + (wn + p * 16 + brow) * PAD + kk + bcol);
            bl[2*p][0] = t[0]; bl[2*p][1] = t[1];
            bl[2*p+1][0] = t[2]; bl[2*p+1][1] = t[3];
        }

        #pragma unroll
        for (int mt = 0; mt < 2; mt++)
            #pragma unroll
            for (int nt = 0; nt < NT; nt++) {
                mma_bf16(acc[mt][nt], ah[mt], bh[nt]);
                mma_bf16(acc[mt][nt], ah[mt], bl[nt]);
                mma_bf16(acc[mt][nt], al[mt], bh[nt]);
            }
    }

    #pragma unroll
    for (int mt = 0; mt < 2; mt++) {
        int r1 = r0 + wm + mt * 16 + (lane >> 2);
        int r2 = r1 + 8;
        #pragma unroll
        for (int nt = 0; nt < NT; nt++) {
            int col = wn + nt * 8 + ((lane & 3) << 1);
            float bx = bias[col], by = bias[col + 1];
            if (r1 < N_NODES)
                *(float2*)&Yout[(size_t)r1 * N + col] =
                    make_float2(acc[mt][nt][0] + bx, acc[mt][nt][1] + by);
            if (r2 < N_NODES)
                *(float2*)&Yout[(size_t)r2 * N + col] =
                    make_float2(acc[mt][nt][2] + bx, acc[mt][nt][3] + by);
        }
    }
}

// ---------------- aggregation: warp per node, 2 edges in flight per warp ----------------
// 16 lanes cover one 256B row (uint4 = 8 halves each); halves 0/1 of the warp
// take even/odd CSR offsets; shfl_xor(16) combines; half 0 writes fp16 H.
template <bool RELU>
__global__ __launch_bounds__(256) void agg_kernel(const float* __restrict__ bias) {
    int gw = (blockIdx.x * 256 + threadIdx.x) >> 5;
    int lane = threadIdx.x & 31;
    if (gw >= N_NODES) return;

    int half_id = lane >> 4;          // 0 or 1
    int sub = lane & 15;              // position within row (8 halves each)

    const uint4* Up = (const uint4*)g_Uh;   // row = 16 uint4

    float acc[8];
    #pragma unroll
    for (int q = 0; q < 8; q++) acc[q] = 0.f;

    // self-loop (half 0 only, counted once)
    if (half_id == 0) {
        uint4 w = Up[(size_t)gw * 16 + sub];
        const __half2* hp = (const __half2*)&w;
        #pragma unroll
        for (int q = 0; q < 4; q++) {
            float2 p = __half22float2(hp[q]);
            acc[2*q]   += p.x;
            acc[2*q+1] += p.y;
        }
    }

    int beg = g_rowstart[gw];
    int end = g_rowstart[gw + 1];

    int j = beg + half_id;
    // unrolled: two edges per half in flight
    for (; j + 2 < end; j += 4) {
        int s0 = g_srcSorted[j];
        int s1 = g_srcSorted[j + 2];
        uint4 w0 = Up[(size_t)s0 * 16 + sub];
        uint4 w1 = Up[(size_t)s1 * 16 + sub];
        const __half2* h0 = (const __half2*)&w0;
        const __half2* h1 = (const __half2*)&w1;
        #pragma unroll
        for (int q = 0; q < 4; q++) {
            float2 p0 = __half22float2(h0[q]);
            float2 p1 = __half22float2(h1[q]);
            acc[2*q]   += p0.x + p1.x;
            acc[2*q+1] += p0.y + p1.y;
        }
    }
    for (; j < end; j += 2) {
        int s = g_srcSorted[j];
        uint4 w = Up[(size_t)s * 16 + sub];
        const __half2* hp = (const __half2*)&w;
        #pragma unroll
        for (int q = 0; q < 4; q++) {
            float2 p = __half22float2(hp[q]);
            acc[2*q]   += p.x;
            acc[2*q+1] += p.y;
        }
    }

    // combine the two halves
    #pragma unroll
    for (int q = 0; q < 8; q++)
        acc[q] += __shfl_xor_sync(0xffffffffu, acc[q], 16);

    if (half_id == 0) {
        float is = g_invs[gw];
        float4 b0 = ((const float4*)bias)[sub * 2];
        float4 b1 = ((const float4*)bias)[sub * 2 + 1];
        float o[8];
        o[0] = is * acc[0] + b0.x;
        o[1] = is * acc[1] + b0.y;
        o[2] = is * acc[2] + b0.z;
        o[3] = is * acc[3] + b0.w;
        o[4] = is * acc[4] + b1.x;
        o[5] = is * acc[5] + b1.y;
        o[6] = is * acc[6] + b1.z;
        o[7] = is * acc[7] + b1.w;
        if (RELU) {
            #pragma unroll
            for (int q = 0; q < 8; q++) o[q] = fmaxf(o[q], 0.f);
        }
        __half2 h0 = __floats2half2_rn(o[0], o[1]);
        __half2 h1 = __floats2half2_rn(o[2], o[3]);
        __half2 h2 = __floats2half2_rn(o[4], o[5]);
        __half2 h3 = __floats2half2_rn(o[6], o[7]);
        uint4 w;
        w.x = *(uint32_t*)&h0;
        w.y = *(uint32_t*)&h1;
        w.z = *(uint32_t*)&h2;
        w.w = *(uint32_t*)&h3;
        *(uint4*)&g_Hh[(size_t)gw * 128 + sub * 8] = w;
    }
}

// ---------------- launch ----------------
extern "C" void kernel_launch(void* const* d_in, const int* in_sizes, int n_in,
                              void* d_out, int out_size)
{
    const float* x  = (const float*)d_in[0];
    const void*  ei = d_in[1];
    const float* W1 = (const float*)d_in[2];
    const float* b1 = (const float*)d_in[3];
    const float* W2 = (const float*)d_in[4];
    const float* b2 = (const float*)d_in[5];
    const float* W3 = (const float*)d_in[6];
    const float* b3 = (const float*)d_in[7];
    const float* Wo = (const float*)d_in[8];
    const float* bo = (const float*)d_in[9];
    float* out = (float*)d_out;

    const int SMEM_F  = 2 * 128 * PAD * 2;                    // 69632 B
    const int SMEM64  = (2 * 128 * PAD + 2 * 64 * PAD) * 2;   // 104448 B
    cudaFuncSetAttribute(gemm_fp16<true>,
                         cudaFuncAttributeMaxDynamicSharedMemorySize, SMEM_F);
    cudaFuncSetAttribute(gemm_fp16<false>,
                         cudaFuncAttributeMaxDynamicSharedMemorySize, SMEM_F);
    cudaFuncSetAttribute(gemm_out,
                         cudaFuncAttributeMaxDynamicSharedMemorySize, SMEM64);

    // graph preprocessing (rebuilt every call; graph-replay deterministic)
    detect_kernel<<<1, 32>>>((const int*)ei);
    reset_kernel<<<(N_NODES + 255) / 256, 256>>>();
    count_kernel<<<(N_EDGES + 255) / 256, 256>>>(ei);
    scan_local_kernel<<<SCAN_NB, 1024>>>();
    scan_bsums_kernel<<<1, 32>>>();
    scan_finalize_kernel<<<(N_NODES + 255) / 256, 256>>>();
    build_kernel<<<(N_EDGES + 255) / 256, 256>>>(ei);

    // weight images
    prep_wf_kernel<<<64, 256>>>(W1, 0);
    prep_wf_kernel<<<64, 256>>>(W2, 16384);
    prep_wf_kernel<<<64, 256>>>(W3, 32768);
    prep_w_kernel<<<32, 256>>>(Wo, 64, WO_HI, WO_LO);

    const int AB = (N_NODES + 7) / 8;

    // layer 1
    gemm_fp16<true><<<NBLK, 256, SMEM_F>>>(x, 0);
    agg_kernel<true><<<AB, 256>>>(b1);
    // layer 2
    gemm_fp16<false><<<NBLK, 256, SMEM_F>>>(nullptr, 16384);
    agg_kernel<true><<<AB, 256>>>(b2);
    // layer 3 (no relu)
    gemm_fp16<false><<<NBLK, 256, SMEM_F>>>(nullptr, 32768);
    agg_kernel<false><<<AB, 256>>>(b3);
    // output projection (bf16 3-pass, fp32 out)
    gemm_out<<<NBLK, 256, SMEM64>>>(bo, out);
}

// round 15
// speedup vs baseline: 2.3187x; 1.0541x over previous
#include <cuda_runtime.h>
#include <cuda_bf16.h>
#include <cuda_fp16.h>
#include <math.h>
#include <stdint.h>

#define N_NODES 100000
#define N_EDGES 1600000
#define NBLK    ((N_NODES + 127) / 128)      // 782
#define SCAN_CHUNK 4096
#define SCAN_NB ((N_NODES + SCAN_CHUNK - 1) / SCAN_CHUNK)   // 25
#define PAD 136   // 16-bit elems per SMEM row: 272B stride -> conflict-free ldmatrix

#define CNT_B   ((N_EDGES + 1023) / 1024)    // 1563 count blocks (4 edges/thread)
#define RESET_B ((N_NODES + 255) / 256)      // 392
#define PREP_B  ((3 * 16384 + 8192 + 255) / 256)  // 224

// ---------------- scratch (static device globals; no allocation) ----------------
__device__ __half g_Uh[(size_t)N_NODES * 128]; // u = (h @ W) (raw for L1, scaled L2/3), fp16
__device__ __half g_Hh[(size_t)N_NODES * 128]; // layer activations, fp16
__device__ __half g_Whf[3 * 16384];            // W1..W3 fp16 images [n][k]
__device__ __nv_bfloat16 g_Wbf[16384];         // Wout bf16 hi/lo images [n][k]
__device__ int   g_srcSorted[N_EDGES];
__device__ int   g_cnt[N_NODES];
__device__ int   g_rowstart[N_NODES + 1];
__device__ int   g_cursor[N_NODES];
__device__ float g_invs[N_NODES];
__device__ int   g_is64;
__device__ int   g_bsum[SCAN_NB];

#define WO_HI 0
#define WO_LO 8192

// ---------------- mma helpers ----------------
__device__ __forceinline__ void ldsm4(uint32_t* r, const void* p) {
    uint32_t a = (uint32_t)__cvta_generic_to_shared(p);
    asm volatile("ldmatrix.sync.aligned.m8n8.x4.shared.b16 {%0,%1,%2,%3}, [%4];"
                 : "=r"(r[0]), "=r"(r[1]), "=r"(r[2]), "=r"(r[3]) : "r"(a));
}

__device__ __forceinline__ void mma_bf16(float* c, const uint32_t* a, const uint32_t* b) {
    asm volatile(
        "mma.sync.aligned.m16n8k16.row.col.f32.bf16.bf16.f32 "
        "{%0,%1,%2,%3}, {%4,%5,%6,%7}, {%8,%9}, {%0,%1,%2,%3};"
        : "+f"(c[0]), "+f"(c[1]), "+f"(c[2]), "+f"(c[3])
        : "r"(a[0]), "r"(a[1]), "r"(a[2]), "r"(a[3]), "r"(b[0]), "r"(b[1]));
}

__device__ __forceinline__ void mma_fp16(float* c, const uint32_t* a, const uint32_t* b) {
    asm volatile(
        "mma.sync.aligned.m16n8k16.row.col.f32.f16.f16.f32 "
        "{%0,%1,%2,%3}, {%4,%5,%6,%7}, {%8,%9}, {%0,%1,%2,%3};"
        : "+f"(c[0]), "+f"(c[1]), "+f"(c[2]), "+f"(c[3])
        : "r"(a[0]), "r"(a[1]), "r"(a[2]), "r"(a[3]), "r"(b[0]), "r"(b[1]));
}

__device__ __forceinline__ int load_idx(const void* ei, long long pos) {
    if (g_is64) return (int)((const long long*)ei)[pos];
    return ((const int*)ei)[pos];
}

// ---------------- K0: reset + weight-image prep + dtype probe (fused) ----------------
__global__ __launch_bounds__(256) void k0_prep(
    const int* __restrict__ ei_raw,
    const float* __restrict__ W1, const float* __restrict__ W2,
    const float* __restrict__ W3, const float* __restrict__ Wo)
{
    int bid = blockIdx.x;
    if (bid < RESET_B) {
        int i = bid * 256 + threadIdx.x;
        if (i < N_NODES) g_cnt[i] = 0;
    } else if (bid < RESET_B + PREP_B) {
        int e = (bid - RESET_B) * 256 + threadIdx.x;
        if (e < 3 * 16384) {
            int layer = e >> 14;
            int elem = e & 16383;
            int k = elem >> 7, n = elem & 127;
            const float* W = (layer == 0) ? W1 : ((layer == 1) ? W2 : W3);
            g_Whf[layer * 16384 + n * 128 + k] = __float2half_rn(W[elem]);
        } else {
            int elem = e - 3 * 16384;       // 0..8191
            int k = elem >> 6, n = elem & 63;
            float v = Wo[elem];
            __nv_bfloat16 hb = __float2bfloat16(v);
            __nv_bfloat16 lb = __float2bfloat16(v - __bfloat162float(hb));
            g_Wbf[WO_HI + n * 128 + k] = hb;
            g_Wbf[WO_LO + n * 128 + k] = lb;
        }
    } else {
        // dtype probe (warp 0 only)
        if (threadIdx.x < 32) {
            int lane = threadIdx.x;
            int bad = 0;
            for (int i = lane; i < 1024; i += 32)
                bad |= (ei_raw[2 * i + 1] != 0);
            unsigned m = __ballot_sync(0xffffffffu, bad);
            if (lane == 0) g_is64 = (m == 0);
        }
    }
}

// ---------------- GEMM core (device fn): D[128,128] tile = X @ W, fp16 mma ----------------
// SCALE: multiply rows by g_invs in epilogue. Output fp16 to g_Uh.
template <bool XEXT, bool SCALE>
__device__ __forceinline__ void gemm_core(int bid, const float* __restrict__ Xext,
                                          int w_off, __half* smh)
{
    __half* Af = smh;                 // [128][PAD]
    __half* Bf = Af + 128 * PAD;      // [128][PAD]

    int tid = threadIdx.x;
    int lane = tid & 31, warp = tid >> 5;
    int r0 = bid * 128;

    if (XEXT) {
        #pragma unroll
        for (int i = 0; i < 16; i++) {
            int j = tid + i * 256;
            int row = j >> 5, c4 = (j & 31) << 2;
            float4 v = make_float4(0.f, 0.f, 0.f, 0.f);
            if (r0 + row < N_NODES)
                v = *(const float4*)&Xext[(size_t)(r0 + row) * 128 + c4];
            __half2 h0 = __floats2half2_rn(v.x, v.y);
            __half2 h1 = __floats2half2_rn(v.z, v.w);
            *(uint2*)&Af[row * PAD + c4] =
                make_uint2(*(uint32_t*)&h0, *(uint32_t*)&h1);
        }
    } else {
        // 128 rows x 16 uint4/row = 2048 uint4
        #pragma unroll
        for (int i = 0; i < 8; i++) {
            int j = tid + i * 256;
            int row = j >> 4, q = j & 15;
            uint4 v = make_uint4(0u, 0u, 0u, 0u);
            if (r0 + row < N_NODES)
                v = *(const uint4*)&g_Hh[(size_t)(r0 + row) * 128 + q * 8];
            *(uint4*)&Af[row * PAD + q * 8] = v;
        }
    }
    #pragma unroll
    for (int i = 0; i < 8; i++) {
        int j = tid + i * 256;
        int row = j >> 4, q = j & 15;
        *(uint4*)&Bf[row * PAD + q * 8] = *(const uint4*)&g_Whf[w_off + row * 128 + q * 8];
    }
    __syncthreads();

    int wm = (warp & 3) * 32;
    int wn = (warp >> 2) * 64;

    float acc[2][8][4];
    #pragma unroll
    for (int mt = 0; mt < 2; mt++)
        #pragma unroll
        for (int nt = 0; nt < 8; nt++)
            #pragma unroll
            for (int q = 0; q < 4; q++) acc[mt][nt][q] = 0.f;

    int arow = lane & 15, acol = (lane >> 4) << 3;
    int brow = (lane & 7) + ((lane >> 4) << 3), bcol = ((lane >> 3) & 1) << 3;

    #pragma unroll
    for (int kk = 0; kk < 128; kk += 16) {
        uint32_t af[2][4];
        ldsm4(af[0], Af + (wm + arow) * PAD + kk + acol);
        ldsm4(af[1], Af + (wm + 16 + arow) * PAD + kk + acol);

        uint32_t bf[8][2];
        #pragma unroll
        for (int p = 0; p < 4; p++) {
            uint32_t t[4];
            ldsm4(t, Bf + (wn + p * 16 + brow) * PAD + kk + bcol);
            bf[2*p][0] = t[0]; bf[2*p][1] = t[1];
            bf[2*p+1][0] = t[2]; bf[2*p+1][1] = t[3];
        }

        #pragma unroll
        for (int mt = 0; mt < 2; mt++)
            #pragma unroll
            for (int nt = 0; nt < 8; nt++)
                mma_fp16(acc[mt][nt], af[mt], bf[nt]);
    }

    #pragma unroll
    for (int mt = 0; mt < 2; mt++) {
        int r1 = r0 + wm + mt * 16 + (lane >> 2);
        int r2 = r1 + 8;
        float s1 = 1.f, s2 = 1.f;
        if (SCALE) {
            s1 = (r1 < N_NODES) ? g_invs[r1] : 0.f;
            s2 = (r2 < N_NODES) ? g_invs[r2] : 0.f;
        }
        #pragma unroll
        for (int nt = 0; nt < 8; nt++) {
            int col = wn + nt * 8 + ((lane & 3) << 1);
            if (r1 < N_NODES)
                *(__half2*)&g_Uh[(size_t)r1 * 128 + col] =
                    __floats2half2_rn(acc[mt][nt][0] * s1, acc[mt][nt][1] * s1);
            if (r2 < N_NODES)
                *(__half2*)&g_Uh[(size_t)r2 * 128 + col] =
                    __floats2half2_rn(acc[mt][nt][2] * s2, acc[mt][nt][3] * s2);
        }
    }
}

// ---------------- K1: degree count + layer-1 GEMM (raw, unscaled) fused ----------------
__global__ __launch_bounds__(256) void k1_count_gemm1(const void* __restrict__ ei,
                                                      const float* __restrict__ x)
{
    extern __shared__ __align__(16) __half smh[];
    int bid = blockIdx.x;
    if (bid < CNT_B) {
        int base = bid * 1024 + threadIdx.x;
        #pragma unroll
        for (int i = 0; i < 4; i++) {
            int e = base + i * 256;
            if (e < N_EDGES) {
                int d = load_idx(ei, (long long)N_EDGES + e);
                if (d >= 0 && d < N_NODES) atomicAdd(&g_cnt[d], 1);
            }
        }
    } else {
        gemm_core<true, false>(bid - CNT_B, x, 0, smh);
    }
}

// ---------------- standalone GEMM (layers 2,3) ----------------
__global__ __launch_bounds__(256) void gemm_fp16_k(int w_off) {
    extern __shared__ __align__(16) __half smh[];
    gemm_core<false, true>(blockIdx.x, nullptr, w_off, smh);
}

// ---------------- scan phase 1 (unchanged) ----------------
__global__ __launch_bounds__(1024) void scan_local_kernel() {
    __shared__ int wsum[32];
    int tid = threadIdx.x, lane = tid & 31, wid = tid >> 5;
    int i0 = blockIdx.x * SCAN_CHUNK + tid * 4;

    int v0 = (i0 + 0 < N_NODES) ? g_cnt[i0 + 0] : 0;
    int v1 = (i0 + 1 < N_NODES) ? g_cnt[i0 + 1] : 0;
    int v2 = (i0 + 2 < N_NODES) ? g_cnt[i0 + 2] : 0;
    int v3 = (i0 + 3 < N_NODES) ? g_cnt[i0 + 3] : 0;
    int t = v0 + v1 + v2 + v3;

    int x = t;
    #pragma unroll
    for (int off = 1; off < 32; off <<= 1) {
        int y = __shfl_up_sync(0xffffffffu, x, off);
        if (lane >= off) x += y;
    }
    if (lane == 31) wsum[wid] = x;
    __syncthreads();
    if (wid == 0) {
        int w = wsum[lane];
        #pragma unroll
        for (int off = 1; off < 32; off <<= 1) {
            int y = __shfl_up_sync(0xffffffffu, w, off);
            if (lane >= off) w += y;
        }
        wsum[lane] = w;
    }
    __syncthreads();

    int run = (wid ? wsum[wid - 1] : 0) + (x - t);
    if (i0 + 0 < N_NODES) { g_rowstart[i0+0] = run; run += v0; }
    if (i0 + 1 < N_NODES) { g_rowstart[i0+1] = run; run += v1; }
    if (i0 + 2 < N_NODES) { g_rowstart[i0+2] = run; run += v2; }
    if (i0 + 3 < N_NODES) { g_rowstart[i0+3] = run; run += v3; }
    if (tid == 0) g_bsum[blockIdx.x] = wsum[31];
}

// ---------------- scan finalize with inline bsums scan ----------------
__global__ __launch_bounds__(256) void scan_finalize_kernel() {
    __shared__ int boff[SCAN_NB];
    __shared__ int s_tot;
    if (threadIdx.x < 32) {
        int lane = threadIdx.x;
        int v = (lane < SCAN_NB) ? g_bsum[lane] : 0;
        int x = v;
        #pragma unroll
        for (int off = 1; off < 32; off <<= 1) {
            int y = __shfl_up_sync(0xffffffffu, x, off);
            if (lane >= off) x += y;
        }
        if (lane < SCAN_NB) boff[lane] = x - v;
        if (lane == 31) s_tot = x;
    }
    __syncthreads();
    int i = blockIdx.x * 256 + threadIdx.x;
    if (i < N_NODES) {
        int v = g_rowstart[i] + boff[i >> 12];
        g_rowstart[i] = v;
        g_cursor[i] = v;
        g_invs[i] = rsqrtf((float)(g_cnt[i] + 1));
    }
    if (i == 0) g_rowstart[N_NODES] = s_tot;
}

__global__ void build_kernel(const void* __restrict__ ei) {
    int e = blockIdx.x * blockDim.x + threadIdx.x;
    if (e < N_EDGES) {
        int s = load_idx(ei, e);
        int d = load_idx(ei, (long long)N_EDGES + e);
        if (s >= 0 && s < N_NODES && d >= 0 && d < N_NODES) {
            int p = atomicAdd(&g_cursor[d], 1);
            if (p >= 0 && p < N_EDGES) g_srcSorted[p] = s;
        }
    }
}

// ---------------- output GEMM: bf16 split 3-pass (N=64), fp32 out + bias ----------------
__global__ __launch_bounds__(256) void gemm_out(const float* __restrict__ bias,
                                                float* __restrict__ Yout) {
    constexpr int N = 64;
    extern __shared__ __align__(16) __nv_bfloat16 sm[];
    __nv_bfloat16* Ah = sm;                         // [128][PAD]
    __nv_bfloat16* Al = Ah + 128 * PAD;
    __nv_bfloat16* Bh = Al + 128 * PAD;             // [N][PAD]
    __nv_bfloat16* Bl = Bh + N * PAD;

    int tid = threadIdx.x;
    int lane = tid & 31, warp = tid >> 5;
    int r0 = blockIdx.x * 128;

    #pragma unroll
    for (int i = 0; i < 16; i++) {
        int j = tid + i * 256;
        int row = j >> 5, c4 = (j & 31) << 2;
        uint2 hv = make_uint2(0u, 0u);
        if (r0 + row < N_NODES)
            hv = *(const uint2*)&g_Hh[(size_t)(r0 + row) * 128 + c4];
        const __half* hp = (const __half*)&hv;
        uint32_t h[4], l[4];
        #pragma unroll
        for (int q = 0; q < 4; q++) {
            float f = __half2float(hp[q]);
            __nv_bfloat16 hb = __float2bfloat16(f);
            h[q] = (uint32_t)__bfloat16_as_ushort(hb);
            l[q] = (uint32_t)__bfloat16_as_ushort(
                       __float2bfloat16(f - __bfloat162float(hb)));
        }
        *(uint2*)&Ah[row * PAD + c4] = make_uint2(h[0] | (h[1] << 16), h[2] | (h[3] << 16));
        *(uint2*)&Al[row * PAD + c4] = make_uint2(l[0] | (l[1] << 16), l[2] | (l[3] << 16));
    }
    #pragma unroll
    for (int i = 0; i < N * 16 / 256; i++) {
        int j = tid + i * 256;
        int row = j >> 4, q = j & 15;
        *(uint4*)&Bh[row * PAD + q * 8] = *(const uint4*)&g_Wbf[WO_HI + row * 128 + q * 8];
        *(uint4*)&Bl[row * PAD + q * 8] = *(const uint4*)&g_Wbf[WO_LO + row * 128 + q * 8];
    }
    __syncthreads();

    constexpr int NT = N / 16;   // 4
    int wm = (warp & 3) * 32;
    int wn = (warp >> 2) * (N / 2);

    float acc[2][NT][4];
    #pragma unroll
    for (int mt = 0; mt < 2; mt++)
        #pragma unroll
        for (int nt = 0; nt < NT; nt++)
            #pragma unroll
            for (int q = 0; q < 4; q++) acc[mt][nt][q] = 0.f;

    int arow = lane & 15, acol = (lane >> 4) << 3;
    int brow = (lane & 7) + ((lane >> 4) << 3), bcol = ((lane >> 3) & 1) << 3;

    #pragma unroll
    for (int kk = 0; kk < 128; kk += 16) {
        uint32_t ah[2][4], al[2][4];
        ldsm4(ah[0], Ah + (wm + arow) * PAD + kk + acol);
        ldsm4(ah[1], Ah + (wm + 16 + arow) * PAD + kk + acol);
        ldsm4(al[0], Al + (wm + arow) * PAD + kk + acol);
        ldsm4(al[1], Al + (wm + 16 + arow) * PAD + kk + acol);

        uint32_t bh[NT][2], bl[NT][2];
        #pragma unroll
        for (int p = 0; p < NT / 2; p++) {
            uint32_t t[4];
            ldsm4(t, Bh + (wn + p * 16 + brow) * PAD + kk + bcol);
            bh[2*p][0] = t[0]; bh[2*p][1] = t[1];
            bh[2*p+1][0] = t[2]; bh[2*p+1][1] = t[3];
            ldsm4(t, Bl + (wn + p * 16 + brow) * PAD + kk + bcol);
            bl[2*p][0] = t[0]; bl[2*p][1] = t[1];
            bl[2*p+1][0] = t[2]; bl[2*p+1][1] = t[3];
        }

        #pragma unroll
        for (int mt = 0; mt < 2; mt++)
            #pragma unroll
            for (int nt = 0; nt < NT; nt++) {
                mma_bf16(acc[mt][nt], ah[mt], bh[nt]);
                mma_bf16(acc[mt][nt], ah[mt], bl[nt]);
                mma_bf16(acc[mt][nt], al[mt], bh[nt]);
            }
    }

    #pragma unroll
    for (int mt = 0; mt < 2; mt++) {
        int r1 = r0 + wm + mt * 16 + (lane >> 2);
        int r2 = r1 + 8;
        #pragma unroll
        for (int nt = 0; nt < NT; nt++) {
            int col = wn + nt * 8 + ((lane & 3) << 1);
            float bx = bias[col], by = bias[col + 1];
            if (r1 < N_NODES)
                *(float2*)&Yout[(size_t)r1 * N + col] =
                    make_float2(acc[mt][nt][0] + bx, acc[mt][nt][1] + by);
            if (r2 < N_NODES)
                *(float2*)&Yout[(size_t)r2 * N + col] =
                    make_float2(acc[mt][nt][2] + bx, acc[mt][nt][3] + by);
        }
    }
}

// ---------------- aggregation: warp per node, 2 halves x 2 edges in flight ----------------
// SRCSCALE: multiply each gathered row by g_invs[src] (layer 1: U is raw XW).
template <bool RELU, bool SRCSCALE>
__global__ __launch_bounds__(256) void agg_kernel(const float* __restrict__ bias) {
    int gw = (blockIdx.x * 256 + threadIdx.x) >> 5;
    int lane = threadIdx.x & 31;
    if (gw >= N_NODES) return;

    int half_id = lane >> 4;          // 0 or 1
    int sub = lane & 15;              // position within row (8 halves each)

    const uint4* Up = (const uint4*)g_Uh;   // row = 16 uint4

    float acc[8];
    #pragma unroll
    for (int q = 0; q < 8; q++) acc[q] = 0.f;

    // self-loop (half 0 only, counted once)
    if (half_id == 0) {
        float sc = SRCSCALE ? g_invs[gw] : 1.f;
        uint4 w = Up[(size_t)gw * 16 + sub];
        const __half2* hp = (const __half2*)&w;
        #pragma unroll
        for (int q = 0; q < 4; q++) {
            float2 p = __half22float2(hp[q]);
            acc[2*q]   = fmaf(sc, p.x, acc[2*q]);
            acc[2*q+1] = fmaf(sc, p.y, acc[2*q+1]);
        }
    }

    int beg = g_rowstart[gw];
    int end = g_rowstart[gw + 1];

    int j = beg + half_id;
    for (; j + 2 < end; j += 4) {
        int s0 = g_srcSorted[j];
        int s1 = g_srcSorted[j + 2];
        float c0 = SRCSCALE ? g_invs[s0] : 1.f;
        float c1 = SRCSCALE ? g_invs[s1] : 1.f;
        uint4 w0 = Up[(size_t)s0 * 16 + sub];
        uint4 w1 = Up[(size_t)s1 * 16 + sub];
        const __half2* h0 = (const __half2*)&w0;
        const __half2* h1 = (const __half2*)&w1;
        #pragma unroll
        for (int q = 0; q < 4; q++) {
            float2 p0 = __half22float2(h0[q]);
            float2 p1 = __half22float2(h1[q]);
            acc[2*q]   = fmaf(c0, p0.x, fmaf(c1, p1.x, acc[2*q]));
            acc[2*q+1] = fmaf(c0, p0.y, fmaf(c1, p1.y, acc[2*q+1]));
        }
    }
    for (; j < end; j += 2) {
        int s = g_srcSorted[j];
        float sc = SRCSCALE ? g_invs[s] : 1.f;
        uint4 w = Up[(size_t)s * 16 + sub];
        const __half2* hp = (const __half2*)&w;
        #pragma unroll
        for (int q = 0; q < 4; q++) {
            float2 p = __half22float2(hp[q]);
            acc[2*q]   = fmaf(sc, p.x, acc[2*q]);
            acc[2*q+1] = fmaf(sc, p.y, acc[2*q+1]);
        }
    }

    // combine the two halves
    #pragma unroll
    for (int q = 0; q < 8; q++)
        acc[q] += __shfl_xor_sync(0xffffffffu, acc[q], 16);

    if (half_id == 0) {
        float is = g_invs[gw];
        float4 b0 = ((const float4*)bias)[sub * 2];
        float4 b1 = ((const float4*)bias)[sub * 2 + 1];
        float o[8];
        o[0] = is * acc[0] + b0.x;
        o[1] = is * acc[1] + b0.y;
        o[2] = is * acc[2] + b0.z;
        o[3] = is * acc[3] + b0.w;
        o[4] = is * acc[4] + b1.x;
        o[5] = is * acc[5] + b1.y;
        o[6] = is * acc[6] + b1.z;
        o[7] = is * acc[7] + b1.w;
        if (RELU) {
            #pragma unroll
            for (int q = 0; q < 8; q++) o[q] = fmaxf(o[q], 0.f);
        }
        __half2 h0 = __floats2half2_rn(o[0], o[1]);
        __half2 h1 = __floats2half2_rn(o[2], o[3]);
        __half2 h2 = __floats2half2_rn(o[4], o[5]);
        __half2 h3 = __floats2half2_rn(o[6], o[7]);
        uint4 w;
        w.x = *(uint32_t*)&h0;
        w.y = *(uint32_t*)&h1;
        w.z = *(uint32_t*)&h2;
        w.w = *(uint32_t*)&h3;
        *(uint4*)&g_Hh[(size_t)gw * 128 + sub * 8] = w;
    }
}

// ---------------- launch ----------------
extern "C" void kernel_launch(void* const* d_in, const int* in_sizes, int n_in,
                              void* d_out, int out_size)
{
    const float* x  = (const float*)d_in[0];
    const void*  ei = d_in[1];
    const float* W1 = (const float*)d_in[2];
    const float* b1 = (const float*)d_in[3];
    const float* W2 = (const float*)d_in[4];
    const float* b2 = (const float*)d_in[5];
    const float* W3 = (const float*)d_in[6];
    const float* b3 = (const float*)d_in[7];
    const float* Wo = (const float*)d_in[8];
    const float* bo = (const float*)d_in[9];
    float* out = (float*)d_out;

    const int SMEM_F  = 2 * 128 * PAD * 2;                    // 69632 B
    const int SMEM64  = (2 * 128 * PAD + 2 * 64 * PAD) * 2;   // 104448 B
    cudaFuncSetAttribute(k1_count_gemm1,
                         cudaFuncAttributeMaxDynamicSharedMemorySize, SMEM_F);
    cudaFuncSetAttribute(gemm_fp16_k,
                         cudaFuncAttributeMaxDynamicSharedMemorySize, SMEM_F);
    cudaFuncSetAttribute(gemm_out,
                         cudaFuncAttributeMaxDynamicSharedMemorySize, SMEM64);

    const int AB = (N_NODES + 7) / 8;

    // K0: reset + weight images + dtype probe
    k0_prep<<<RESET_B + PREP_B + 1, 256>>>((const int*)ei, W1, W2, W3, Wo);
    // K1: degree count + layer-1 GEMM (raw XW, fp16)
    k1_count_gemm1<<<CNT_B + NBLK, 256, SMEM_F>>>(ei, x);
    // CSR scan + build
    scan_local_kernel<<<SCAN_NB, 1024>>>();
    scan_finalize_kernel<<<(N_NODES + 255) / 256, 256>>>();
    build_kernel<<<(N_EDGES + 255) / 256, 256>>>(ei);

    // layer 1 aggregation (applies invs[src] per edge)
    agg_kernel<true, true><<<AB, 256>>>(b1);
    // layer 2
    gemm_fp16_k<<<NBLK, 256, SMEM_F>>>(16384);
    agg_kernel<true, false><<<AB, 256>>>(b2);
    // layer 3 (no relu)
    gemm_fp16_k<<<NBLK, 256, SMEM_F>>>(32768);
    agg_kernel<false, false><<<AB, 256>>>(b3);
    // output projection (bf16 3-pass, fp32 out)
    gemm_out<<<NBLK, 256, SMEM64>>>(bo, out);
}